// round 2
// baseline (speedup 1.0000x reference)
#include <cuda_runtime.h>

#define HW 65536
#define CN 64
#define C2 128
#define NB 8
#define EPSV 1e-6f

// ---------------- scratch (device globals; no cudaMalloc allowed) ----------------
__device__ float  g_u [(size_t)NB*C2*HW];   // pw1 output (pre-dwconv), 268MB
__device__ float  g_g [(size_t)NB*CN*HW];   // gated (pre-SCA-scale), 134MB
__device__ float  g_x1[(size_t)NB*CN*HW];   // first residual output, 134MB
__device__ float  g_mean1[NB*CN];
__device__ float  g_rstd1[NB*CN];
__device__ float  g_pool [NB*CN];
__device__ float  g_sum2 [NB*CN];
__device__ float  g_sumsq2[NB*CN];
__device__ float2 g_w1d[NB*CN*C2];          // LN1-folded pw1 weights, duplicated (w,w), [n][i][o]
__device__ float  g_b1e[NB*C2];
__device__ float2 g_w2d[NB*CN*CN];          // SCA-scale-folded pw2 weights, [n][i][o]
__device__ float2 g_w3d[NB*CN*C2];          // LN2-folded pw3 weights, [n][i][o]
__device__ float  g_b3e[NB*C2];
__device__ float2 g_w4d[CN*CN];             // pw4 duplicated, [i][o]

// ---------------- packed fp32x2 FMA (2 MACs/instruction on sm_103a) --------------
__device__ __forceinline__ unsigned long long ffma2(unsigned long long a,
                                                    unsigned long long b,
                                                    unsigned long long c) {
    unsigned long long d;
    asm("fma.rn.f32x2 %0, %1, %2, %3;" : "=l"(d) : "l"(a), "l"(b), "l"(c));
    return d;
}
__device__ __forceinline__ float2 unpack2(unsigned long long v) {
    float2 r;
    r.x = __uint_as_float((unsigned)(v & 0xffffffffull));
    r.y = __uint_as_float((unsigned)(v >> 32));
    return r;
}

// ---------------- K1: LN1 stats over HW per (n,c) --------------------------------
__global__ void k_stats1(const float* __restrict__ x) {
    int nc = blockIdx.x;
    const float4* p = (const float4*)(x + (size_t)nc * HW);
    float s = 0.f, q = 0.f;
    for (int j = threadIdx.x; j < HW / 4; j += 256) {
        float4 v = p[j];
        s += v.x + v.y + v.z + v.w;
        q += v.x * v.x + v.y * v.y + v.z * v.z + v.w * v.w;
    }
    __shared__ float rs[8], rq[8];
    for (int o = 16; o; o >>= 1) {
        s += __shfl_down_sync(0xffffffffu, s, o);
        q += __shfl_down_sync(0xffffffffu, q, o);
    }
    if ((threadIdx.x & 31) == 0) { rs[threadIdx.x >> 5] = s; rq[threadIdx.x >> 5] = q; }
    __syncthreads();
    if (threadIdx.x == 0) {
        float S = 0.f, Q = 0.f;
        for (int i = 0; i < 8; i++) { S += rs[i]; Q += rq[i]; }
        float m = S * (1.f / HW);
        float var = Q * (1.f / HW) - m * m;
        g_mean1[nc] = m;
        g_rstd1[nc] = rsqrtf(var + EPSV);
    }
}

// ---------------- K2: fold LN1 into pw1, zero accumulators -----------------------
__global__ void k_prep1(const float* __restrict__ ln1w, const float* __restrict__ ln1b,
                        const float* __restrict__ pw1w, const float* __restrict__ pw1b) {
    int n = blockIdx.x, o = threadIdx.x;   // 128 threads
    float bias = pw1b[o];
    for (int i = 0; i < CN; i++) {
        float a  = g_rstd1[n * CN + i] * ln1w[i];
        float c0 = ln1b[i] - g_mean1[n * CN + i] * a;
        float w  = pw1w[o * CN + i];
        bias += w * c0;
        float we = w * a;
        g_w1d[(n * CN + i) * C2 + o] = make_float2(we, we);
    }
    g_b1e[n * C2 + o] = bias;
    int idx = n * C2 + o;
    if (idx < NB * CN) { g_pool[idx] = 0.f; g_sum2[idx] = 0.f; g_sumsq2[idx] = 0.f; }
}

// ---------------- K3: pw1 GEMM (LN folded), u = W1eff @ x + b1eff ----------------
__global__ void __launch_bounds__(512) k_pw1(const float* __restrict__ x) {
    extern __shared__ float sm[];
    float*  xs = sm;                       // [64][128]
    float2* wd = (float2*)(sm + CN * 128); // [64][128] duplicated
    int n = blockIdx.y;
    int p0 = blockIdx.x * 128;
    int t = threadIdx.x;
    {
        const float4* src = (const float4*)(x + (size_t)n * CN * HW);
        float4* dst = (float4*)xs;
        #pragma unroll
        for (int k = 0; k < 4; k++) {
            int idx = t + k * 512;
            int i = idx >> 5, px4 = idx & 31;
            dst[idx] = src[(size_t)i * (HW / 4) + (p0 >> 2) + px4];
        }
        const float4* wsrc = (const float4*)(g_w1d + n * CN * C2);
        float4* wdst = (float4*)wd;
        #pragma unroll
        for (int k = 0; k < 8; k++) wdst[t + k * 512] = wsrc[t + k * 512];
    }
    __syncthreads();
    int o0 = (t >> 5) * 8;
    int px = (t & 31) * 4;
    unsigned long long acc[16];
    #pragma unroll
    for (int c = 0; c < 16; c++) acc[c] = 0ull;
    #pragma unroll 8
    for (int i = 0; i < CN; i++) {
        const ulonglong2* wr = (const ulonglong2*)(wd + i * C2 + o0);
        ulonglong2 w0 = wr[0], w1 = wr[1], w2 = wr[2], w3 = wr[3];
        ulonglong2 xv = *(const ulonglong2*)(xs + i * 128 + px);
        unsigned long long xp0 = xv.x, xp1 = xv.y;
        acc[0]  = ffma2(w0.x, xp0, acc[0]);  acc[1]  = ffma2(w0.x, xp1, acc[1]);
        acc[2]  = ffma2(w0.y, xp0, acc[2]);  acc[3]  = ffma2(w0.y, xp1, acc[3]);
        acc[4]  = ffma2(w1.x, xp0, acc[4]);  acc[5]  = ffma2(w1.x, xp1, acc[5]);
        acc[6]  = ffma2(w1.y, xp0, acc[6]);  acc[7]  = ffma2(w1.y, xp1, acc[7]);
        acc[8]  = ffma2(w2.x, xp0, acc[8]);  acc[9]  = ffma2(w2.x, xp1, acc[9]);
        acc[10] = ffma2(w2.y, xp0, acc[10]); acc[11] = ffma2(w2.y, xp1, acc[11]);
        acc[12] = ffma2(w3.x, xp0, acc[12]); acc[13] = ffma2(w3.x, xp1, acc[13]);
        acc[14] = ffma2(w3.y, xp0, acc[14]); acc[15] = ffma2(w3.y, xp1, acc[15]);
    }
    #pragma unroll
    for (int c = 0; c < 8; c++) {
        float b = g_b1e[n * C2 + o0 + c];
        float2 lo = unpack2(acc[2 * c]), hi = unpack2(acc[2 * c + 1]);
        float4 out = make_float4(lo.x + b, lo.y + b, hi.x + b, hi.y + b);
        *(float4*)(g_u + ((size_t)(n * C2 + o0 + c)) * HW + p0 + px) = out;
    }
}

// ---------------- K4: depthwise 3x3 + gate + SCA pool partials -------------------
__global__ void __launch_bounds__(256) k_dwgate(const float* __restrict__ dww,
                                                const float* __restrict__ dwb) {
    __shared__ float sw[C2 * 9];
    __shared__ float sb[C2];
    __shared__ float su0[10 * 66];
    __shared__ float su1[10 * 66];
    __shared__ float red[8];
    int t = threadIdx.x;
    for (int idx = t; idx < C2 * 9; idx += 256) sw[idx] = dww[idx];
    if (t < C2) sb[t] = dwb[t];
    int n  = blockIdx.z;
    int h0 = blockIdx.y * 8;
    int w0 = blockIdx.x * 64;
    int tx = t & 63, ty = t >> 6;
    for (int c = 0; c < CN; c++) {
        const float* u0 = g_u + ((size_t)(n * C2 + c)) * HW;
        const float* u1 = g_u + ((size_t)(n * C2 + c + 64)) * HW;
        for (int idx = t; idx < 660; idx += 256) {
            int r = idx / 66, col = idx - r * 66;
            int gh = h0 - 1 + r, gw = w0 - 1 + col;
            bool ok = ((unsigned)gh < 256u) && ((unsigned)gw < 256u);
            int gi = gh * 256 + gw;
            su0[idx] = ok ? u0[gi] : 0.f;
            su1[idx] = ok ? u1[gi] : 0.f;
        }
        __syncthreads();
        float psum = 0.f;
        #pragma unroll
        for (int rr = 0; rr < 2; rr++) {
            int y = ty + rr * 4;
            float a0 = sb[c], a1 = sb[c + 64];
            #pragma unroll
            for (int ky = 0; ky < 3; ky++)
                #pragma unroll
                for (int kx = 0; kx < 3; kx++) {
                    a0 += sw[c * 9 + ky * 3 + kx]        * su0[(y + ky) * 66 + tx + kx];
                    a1 += sw[(c + 64) * 9 + ky * 3 + kx] * su1[(y + ky) * 66 + tx + kx];
                }
            float gv = a0 * a1;
            g_g[((size_t)(n * CN + c)) * HW + (h0 + y) * 256 + w0 + tx] = gv;
            psum += gv;
        }
        for (int o = 16; o; o >>= 1) psum += __shfl_down_sync(0xffffffffu, psum, o);
        if ((t & 31) == 0) red[t >> 5] = psum;
        __syncthreads();
        if (t < 8) {
            float v = red[t];
            v += __shfl_down_sync(0xffu, v, 4);
            v += __shfl_down_sync(0xffu, v, 2);
            v += __shfl_down_sync(0xffu, v, 1);
            if (t == 0) atomicAdd(&g_pool[n * CN + c], v);
        }
        __syncthreads();   // protect su/red before next iteration
    }
}

// ---------------- K5: SCA sigmoid, fold scale into pw2 weights -------------------
__global__ void k_sca(const float* __restrict__ scaw, const float* __restrict__ scab,
                      const float* __restrict__ pw2w) {
    int n = blockIdx.x, o = threadIdx.x;   // 64 threads
    __shared__ float pm[CN], sc[CN];
    pm[o] = g_pool[n * CN + o] * (1.f / HW);
    __syncthreads();
    float acc = scab[o];
    for (int i = 0; i < CN; i++) acc += scaw[o * CN + i] * pm[i];
    sc[o] = 1.f / (1.f + expf(-acc));
    __syncthreads();
    for (int i = 0; i < CN; i++) {
        float we = pw2w[o * CN + i] * sc[i];
        g_w2d[(n * CN + i) * CN + o] = make_float2(we, we);
    }
}

// ---------------- K6: pw2 GEMM + residual + LN2 stats accumulation ---------------
__global__ void __launch_bounds__(512) k_pw2(const float* __restrict__ x,
                                             const float* __restrict__ pw2b,
                                             const float* __restrict__ beta1) {
    extern __shared__ float sm[];
    float*  gs = sm;                       // [64][128]
    float2* wd = (float2*)(sm + CN * 128); // [64][64]
    __shared__ float s_sum[CN], s_sq[CN];
    int n = blockIdx.y;
    int p0 = blockIdx.x * 128;
    int t = threadIdx.x;
    if (t < CN) { s_sum[t] = 0.f; s_sq[t] = 0.f; }
    {
        const float4* src = (const float4*)(g_g + (size_t)n * CN * HW);
        float4* dst = (float4*)gs;
        #pragma unroll
        for (int k = 0; k < 4; k++) {
            int idx = t + k * 512;
            int i = idx >> 5, px4 = idx & 31;
            dst[idx] = src[(size_t)i * (HW / 4) + (p0 >> 2) + px4];
        }
        const float4* wsrc = (const float4*)(g_w2d + n * CN * CN);
        float4* wdst = (float4*)wd;
        #pragma unroll
        for (int k = 0; k < 4; k++) wdst[t + k * 512] = wsrc[t + k * 512];
    }
    __syncthreads();
    int o0 = (t >> 5) * 4;
    int px = (t & 31) * 4;
    unsigned long long acc[8];
    #pragma unroll
    for (int c = 0; c < 8; c++) acc[c] = 0ull;
    #pragma unroll 8
    for (int i = 0; i < CN; i++) {
        const ulonglong2* wr = (const ulonglong2*)(wd + i * CN + o0);
        ulonglong2 w0 = wr[0], w1 = wr[1];
        ulonglong2 xv = *(const ulonglong2*)(gs + i * 128 + px);
        unsigned long long xp0 = xv.x, xp1 = xv.y;
        acc[0] = ffma2(w0.x, xp0, acc[0]); acc[1] = ffma2(w0.x, xp1, acc[1]);
        acc[2] = ffma2(w0.y, xp0, acc[2]); acc[3] = ffma2(w0.y, xp1, acc[3]);
        acc[4] = ffma2(w1.x, xp0, acc[4]); acc[5] = ffma2(w1.x, xp1, acc[5]);
        acc[6] = ffma2(w1.y, xp0, acc[6]); acc[7] = ffma2(w1.y, xp1, acc[7]);
    }
    #pragma unroll
    for (int c = 0; c < 4; c++) {
        int o = o0 + c;
        float b = pw2b[o], bt = beta1[o];
        float2 lo = unpack2(acc[2 * c]), hi = unpack2(acc[2 * c + 1]);
        size_t off = ((size_t)(n * CN + o)) * HW + p0 + px;
        float4 xv = *(const float4*)(x + off);
        float4 r;
        r.x = xv.x + bt * (lo.x + b);
        r.y = xv.y + bt * (lo.y + b);
        r.z = xv.z + bt * (hi.x + b);
        r.w = xv.w + bt * (hi.y + b);
        *(float4*)(g_x1 + off) = r;
        float ls = r.x + r.y + r.z + r.w;
        float lq = r.x * r.x + r.y * r.y + r.z * r.z + r.w * r.w;
        for (int of = 16; of; of >>= 1) {
            ls += __shfl_down_sync(0xffffffffu, ls, of);
            lq += __shfl_down_sync(0xffffffffu, lq, of);
        }
        if ((t & 31) == 0) { atomicAdd(&s_sum[o], ls); atomicAdd(&s_sq[o], lq); }
    }
    __syncthreads();
    if (t < CN) {
        atomicAdd(&g_sum2[n * CN + t],   s_sum[t]);
        atomicAdd(&g_sumsq2[n * CN + t], s_sq[t]);
    }
}

// ---------------- K7: LN2 finalize + fold into pw3; duplicate pw4 ----------------
__global__ void k_prep3(const float* __restrict__ ln2w, const float* __restrict__ ln2b,
                        const float* __restrict__ pw3w, const float* __restrict__ pw3b,
                        const float* __restrict__ pw4w) {
    int n = blockIdx.x, o = threadIdx.x;   // 128 threads
    __shared__ float m2[CN], r2[CN];
    if (o < CN) {
        float m = g_sum2[n * CN + o] * (1.f / HW);
        float var = g_sumsq2[n * CN + o] * (1.f / HW) - m * m;
        m2[o] = m;
        r2[o] = rsqrtf(var + EPSV);
    }
    __syncthreads();
    float bias = pw3b[o];
    for (int i = 0; i < CN; i++) {
        float a  = r2[i] * ln2w[i];
        float c0 = ln2b[i] - m2[i] * a;
        float w  = pw3w[o * CN + i];
        bias += w * c0;
        float we = w * a;
        g_w3d[(n * CN + i) * C2 + o] = make_float2(we, we);
    }
    g_b3e[n * C2 + o] = bias;
    if (n == 0 && o < CN) {
        for (int i = 0; i < CN; i++) {
            float w = pw4w[o * CN + i];
            g_w4d[i * CN + o] = make_float2(w, w);
        }
    }
}

// ---------------- K8: pw3 GEMM -> gate -> pw4 GEMM -> residual -> out ------------
__global__ void __launch_bounds__(512) k_final(const float* __restrict__ pw4b,
                                               const float* __restrict__ beta2,
                                               float* __restrict__ out) {
    extern __shared__ float sm[];
    float*  xs = sm;                                   // 8192 floats (x1 tile)
    float2* w3 = (float2*)(sm + 8192);                 // 8192 float2
    float*  us = sm + 8192 + 16384;                    // 16384 floats
    float2* w4 = (float2*)(sm + 8192 + 16384 + 16384); // 4096 float2
    int n = blockIdx.y;
    int p0 = blockIdx.x * 128;
    int t = threadIdx.x;
    {
        const float4* src = (const float4*)(g_x1 + (size_t)n * CN * HW);
        float4* dst = (float4*)xs;
        #pragma unroll
        for (int k = 0; k < 4; k++) {
            int idx = t + k * 512;
            int i = idx >> 5, px4 = idx & 31;
            dst[idx] = src[(size_t)i * (HW / 4) + (p0 >> 2) + px4];
        }
        const float4* w3s = (const float4*)(g_w3d + n * CN * C2);
        float4* w3dst = (float4*)w3;
        #pragma unroll
        for (int k = 0; k < 8; k++) w3dst[t + k * 512] = w3s[t + k * 512];
        const float4* w4s = (const float4*)g_w4d;
        float4* w4dst = (float4*)w4;
        #pragma unroll
        for (int k = 0; k < 4; k++) w4dst[t + k * 512] = w4s[t + k * 512];
    }
    __syncthreads();
    int px = (t & 31) * 4;
    // Phase A: pw3 (LN2 folded) -> us
    {
        int o0 = (t >> 5) * 8;
        unsigned long long acc[16];
        #pragma unroll
        for (int c = 0; c < 16; c++) acc[c] = 0ull;
        #pragma unroll 8
        for (int i = 0; i < CN; i++) {
            const ulonglong2* wr = (const ulonglong2*)(w3 + i * C2 + o0);
            ulonglong2 w0 = wr[0], w1 = wr[1], w2 = wr[2], wv3 = wr[3];
            ulonglong2 xv = *(const ulonglong2*)(xs + i * 128 + px);
            unsigned long long xp0 = xv.x, xp1 = xv.y;
            acc[0]  = ffma2(w0.x, xp0, acc[0]);  acc[1]  = ffma2(w0.x, xp1, acc[1]);
            acc[2]  = ffma2(w0.y, xp0, acc[2]);  acc[3]  = ffma2(w0.y, xp1, acc[3]);
            acc[4]  = ffma2(w1.x, xp0, acc[4]);  acc[5]  = ffma2(w1.x, xp1, acc[5]);
            acc[6]  = ffma2(w1.y, xp0, acc[6]);  acc[7]  = ffma2(w1.y, xp1, acc[7]);
            acc[8]  = ffma2(w2.x, xp0, acc[8]);  acc[9]  = ffma2(w2.x, xp1, acc[9]);
            acc[10] = ffma2(w2.y, xp0, acc[10]); acc[11] = ffma2(w2.y, xp1, acc[11]);
            acc[12] = ffma2(wv3.x, xp0, acc[12]); acc[13] = ffma2(wv3.x, xp1, acc[13]);
            acc[14] = ffma2(wv3.y, xp0, acc[14]); acc[15] = ffma2(wv3.y, xp1, acc[15]);
        }
        #pragma unroll
        for (int c = 0; c < 8; c++) {
            float b = g_b3e[n * C2 + o0 + c];
            float2 lo = unpack2(acc[2 * c]), hi = unpack2(acc[2 * c + 1]);
            *(float4*)(us + (o0 + c) * 128 + px) = make_float4(lo.x + b, lo.y + b, hi.x + b, hi.y + b);
        }
    }
    __syncthreads();
    // Gate in place: us[c] *= us[c+64]  (c < 64)
    {
        float4* us4 = (float4*)us;
        #pragma unroll
        for (int k = 0; k < 4; k++) {
            int idx = t + k * 512;          // 2048 float4s over c<64
            int c = idx >> 5, q = idx & 31;
            float4 a = us4[c * 32 + q];
            float4 b = us4[(c + 64) * 32 + q];
            us4[c * 32 + q] = make_float4(a.x * b.x, a.y * b.y, a.z * b.z, a.w * b.w);
        }
    }
    __syncthreads();
    // Phase B: pw4 + residual + store
    {
        int o0 = (t >> 5) * 4;
        unsigned long long acc[8];
        #pragma unroll
        for (int c = 0; c < 8; c++) acc[c] = 0ull;
        #pragma unroll 8
        for (int i = 0; i < CN; i++) {
            const ulonglong2* wr = (const ulonglong2*)(w4 + i * CN + o0);
            ulonglong2 w0 = wr[0], w1 = wr[1];
            ulonglong2 xv = *(const ulonglong2*)(us + i * 128 + px);
            unsigned long long xp0 = xv.x, xp1 = xv.y;
            acc[0] = ffma2(w0.x, xp0, acc[0]); acc[1] = ffma2(w0.x, xp1, acc[1]);
            acc[2] = ffma2(w0.y, xp0, acc[2]); acc[3] = ffma2(w0.y, xp1, acc[3]);
            acc[4] = ffma2(w1.x, xp0, acc[4]); acc[5] = ffma2(w1.x, xp1, acc[5]);
            acc[6] = ffma2(w1.y, xp0, acc[6]); acc[7] = ffma2(w1.y, xp1, acc[7]);
        }
        #pragma unroll
        for (int c = 0; c < 4; c++) {
            int o = o0 + c;
            float b = pw4b[o], bt = beta2[o];
            float2 lo = unpack2(acc[2 * c]), hi = unpack2(acc[2 * c + 1]);
            float4 x1v = *(const float4*)(xs + o * 128 + px);
            float4 r;
            r.x = x1v.x + bt * (lo.x + b);
            r.y = x1v.y + bt * (lo.y + b);
            r.z = x1v.z + bt * (hi.x + b);
            r.w = x1v.w + bt * (hi.y + b);
            *(float4*)(out + ((size_t)(n * CN + o)) * HW + p0 + px) = r;
        }
    }
}

// ---------------- host ------------------------------------------------------------
extern "C" void kernel_launch(void* const* d_in, const int* in_sizes, int n_in,
                              void* d_out, int out_size) {
    const float* x     = (const float*)d_in[0];
    const float* ln1w  = (const float*)d_in[1];
    const float* ln1b  = (const float*)d_in[2];
    const float* pw1w  = (const float*)d_in[3];
    const float* pw1b  = (const float*)d_in[4];
    const float* dww   = (const float*)d_in[5];
    const float* dwb   = (const float*)d_in[6];
    const float* scaw  = (const float*)d_in[7];
    const float* scab  = (const float*)d_in[8];
    const float* pw2w  = (const float*)d_in[9];
    const float* pw2b  = (const float*)d_in[10];
    const float* ln2w  = (const float*)d_in[11];
    const float* ln2b  = (const float*)d_in[12];
    const float* pw3w  = (const float*)d_in[13];
    const float* pw3b  = (const float*)d_in[14];
    const float* pw4w  = (const float*)d_in[15];
    const float* pw4b  = (const float*)d_in[16];
    const float* beta1 = (const float*)d_in[17];
    const float* beta2 = (const float*)d_in[18];

    cudaFuncSetAttribute(k_pw1,   cudaFuncAttributeMaxDynamicSharedMemorySize, 96 * 1024);
    cudaFuncSetAttribute(k_pw2,   cudaFuncAttributeMaxDynamicSharedMemorySize, 64 * 1024);
    cudaFuncSetAttribute(k_final, cudaFuncAttributeMaxDynamicSharedMemorySize, 192 * 1024);

    k_stats1<<<NB * CN, 256>>>(x);
    k_prep1<<<NB, C2>>>(ln1w, ln1b, pw1w, pw1b);
    k_pw1<<<dim3(512, NB), 512, 96 * 1024>>>(x);
    k_dwgate<<<dim3(4, 32, NB), 256>>>(dww, dwb);
    k_sca<<<NB, CN>>>(scaw, scab, pw2w);
    k_pw2<<<dim3(512, NB), 512, 64 * 1024>>>(x, pw2b, beta1);
    k_prep3<<<NB, C2>>>(ln2w, ln2b, pw3w, pw3b, pw4w);
    k_final<<<dim3(512, NB), 512, 192 * 1024>>>(pw4b, beta2, (float*)d_out);
}

// round 4
// speedup vs baseline: 1.1381x; 1.1381x over previous
#include <cuda_runtime.h>

#define HW 65536
#define CN 64
#define C2 128
#define NB 8
#define EPSV 1e-6f

// ---------------- scratch (device globals; no cudaMalloc allowed) ----------------
__device__ float  g_u [(size_t)NB*C2*HW];   // pw1 output (pre-dwconv), 268MB
__device__ float  g_g [(size_t)NB*CN*HW];   // gated (pre-SCA-scale), 134MB
__device__ float  g_x1[(size_t)NB*CN*HW];   // first residual output, 134MB
__device__ float  g_mean1[NB*CN];
__device__ float  g_rstd1[NB*CN];
__device__ float  g_pool [NB*CN];
__device__ float  g_sum2 [NB*CN];
__device__ float  g_sumsq2[NB*CN];
__device__ float2 g_w1d[NB*CN*C2];          // LN1-folded pw1 weights, duplicated (w,w), [n][i][o]
__device__ float  g_b1e[NB*C2];
__device__ float2 g_w2d[NB*CN*CN];          // SCA-scale-folded pw2 weights, [n][i][o]
__device__ float2 g_w3d[NB*CN*C2];          // LN2-folded pw3 weights, [n][i][o]
__device__ float  g_b3e[NB*C2];
__device__ float2 g_w4d[CN*CN];             // pw4 duplicated, [i][o]

// ---------------- packed fp32x2 FMA (2 MACs/instruction on sm_103a) --------------
__device__ __forceinline__ unsigned long long ffma2(unsigned long long a,
                                                    unsigned long long b,
                                                    unsigned long long c) {
    unsigned long long d;
    asm("fma.rn.f32x2 %0, %1, %2, %3;" : "=l"(d) : "l"(a), "l"(b), "l"(c));
    return d;
}
__device__ __forceinline__ float2 unpack2(unsigned long long v) {
    float2 r;
    r.x = __uint_as_float((unsigned)(v & 0xffffffffull));
    r.y = __uint_as_float((unsigned)(v >> 32));
    return r;
}

// ---------------- K1: LN1 stats over HW per (n,c) --------------------------------
__global__ void k_stats1(const float* __restrict__ x) {
    int nc = blockIdx.x;
    const float4* p = (const float4*)(x + (size_t)nc * HW);
    float s = 0.f, q = 0.f;
    for (int j = threadIdx.x; j < HW / 4; j += 256) {
        float4 v = p[j];
        s += v.x + v.y + v.z + v.w;
        q += v.x * v.x + v.y * v.y + v.z * v.z + v.w * v.w;
    }
    __shared__ float rs[8], rq[8];
    for (int o = 16; o; o >>= 1) {
        s += __shfl_down_sync(0xffffffffu, s, o);
        q += __shfl_down_sync(0xffffffffu, q, o);
    }
    if ((threadIdx.x & 31) == 0) { rs[threadIdx.x >> 5] = s; rq[threadIdx.x >> 5] = q; }
    __syncthreads();
    if (threadIdx.x == 0) {
        float S = 0.f, Q = 0.f;
        for (int i = 0; i < 8; i++) { S += rs[i]; Q += rq[i]; }
        float m = S * (1.f / HW);
        float var = Q * (1.f / HW) - m * m;
        g_mean1[nc] = m;
        g_rstd1[nc] = rsqrtf(var + EPSV);
    }
}

// ---------------- K2: fold LN1 into pw1, zero accumulators -----------------------
__global__ void k_prep1(const float* __restrict__ ln1w, const float* __restrict__ ln1b,
                        const float* __restrict__ pw1w, const float* __restrict__ pw1b) {
    int n = blockIdx.x, o = threadIdx.x;   // 128 threads
    float bias = pw1b[o];
    for (int i = 0; i < CN; i++) {
        float a  = g_rstd1[n * CN + i] * ln1w[i];
        float c0 = ln1b[i] - g_mean1[n * CN + i] * a;
        float w  = pw1w[o * CN + i];
        bias += w * c0;
        float we = w * a;
        g_w1d[(n * CN + i) * C2 + o] = make_float2(we, we);
    }
    g_b1e[n * C2 + o] = bias;
    int idx = n * C2 + o;
    if (idx < NB * CN) { g_pool[idx] = 0.f; g_sum2[idx] = 0.f; g_sumsq2[idx] = 0.f; }
}

// ---------------- K3: pw1 GEMM (LN folded), u = W1eff @ x + b1eff ----------------
__global__ void __launch_bounds__(512) k_pw1(const float* __restrict__ x) {
    extern __shared__ float sm[];
    float*  xs = sm;                       // [64][128]
    float2* wd = (float2*)(sm + CN * 128); // [64][128] duplicated
    int n = blockIdx.y;
    int p0 = blockIdx.x * 128;
    int t = threadIdx.x;
    {
        const float4* src = (const float4*)(x + (size_t)n * CN * HW);
        float4* dst = (float4*)xs;
        #pragma unroll
        for (int k = 0; k < 4; k++) {
            int idx = t + k * 512;
            int i = idx >> 5, px4 = idx & 31;
            dst[idx] = src[(size_t)i * (HW / 4) + (p0 >> 2) + px4];
        }
        const float4* wsrc = (const float4*)(g_w1d + n * CN * C2);
        float4* wdst = (float4*)wd;
        #pragma unroll
        for (int k = 0; k < 8; k++) wdst[t + k * 512] = wsrc[t + k * 512];
    }
    __syncthreads();
    int o0 = (t >> 5) * 8;
    int px = (t & 31) * 4;
    unsigned long long acc[16];
    #pragma unroll
    for (int c = 0; c < 16; c++) acc[c] = 0ull;
    #pragma unroll 8
    for (int i = 0; i < CN; i++) {
        const ulonglong2* wr = (const ulonglong2*)(wd + i * C2 + o0);
        ulonglong2 w0 = wr[0], w1 = wr[1], w2 = wr[2], w3 = wr[3];
        ulonglong2 xv = *(const ulonglong2*)(xs + i * 128 + px);
        unsigned long long xp0 = xv.x, xp1 = xv.y;
        acc[0]  = ffma2(w0.x, xp0, acc[0]);  acc[1]  = ffma2(w0.x, xp1, acc[1]);
        acc[2]  = ffma2(w0.y, xp0, acc[2]);  acc[3]  = ffma2(w0.y, xp1, acc[3]);
        acc[4]  = ffma2(w1.x, xp0, acc[4]);  acc[5]  = ffma2(w1.x, xp1, acc[5]);
        acc[6]  = ffma2(w1.y, xp0, acc[6]);  acc[7]  = ffma2(w1.y, xp1, acc[7]);
        acc[8]  = ffma2(w2.x, xp0, acc[8]);  acc[9]  = ffma2(w2.x, xp1, acc[9]);
        acc[10] = ffma2(w2.y, xp0, acc[10]); acc[11] = ffma2(w2.y, xp1, acc[11]);
        acc[12] = ffma2(w3.x, xp0, acc[12]); acc[13] = ffma2(w3.x, xp1, acc[13]);
        acc[14] = ffma2(w3.y, xp0, acc[14]); acc[15] = ffma2(w3.y, xp1, acc[15]);
    }
    #pragma unroll
    for (int c = 0; c < 8; c++) {
        float b = g_b1e[n * C2 + o0 + c];
        float2 lo = unpack2(acc[2 * c]), hi = unpack2(acc[2 * c + 1]);
        float4 out = make_float4(lo.x + b, lo.y + b, hi.x + b, hi.y + b);
        *(float4*)(g_u + ((size_t)(n * C2 + o0 + c)) * HW + p0 + px) = out;
    }
}

// ---------------- K4: depthwise 3x3 + gate + SCA pool partials (row-streaming) ---
// One block = one (n, channel-pair) x 32-row strip. 256 threads = 64 col-quads x 4 rows.
// 8-slot smem row ring per channel; 4 fresh rows loaded per iteration.
__global__ void __launch_bounds__(256) k_dwgate(const float* __restrict__ dww,
                                                const float* __restrict__ dwb) {
    __shared__ float s[2][8][256];
    __shared__ float red[8];
    int t = threadIdx.x;
    int tx = t & 63, ty = t >> 6;
    int nc = blockIdx.x;                  // n*64 + c
    int n = nc >> 6, c = nc & 63;
    int strip0 = blockIdx.y * 32;

    const float* u0 = g_u + ((size_t)(n * C2 + c)) * HW;
    const float* u1 = g_u + ((size_t)(n * C2 + c + 64)) * HW;
    float*       gp = g_g + ((size_t)(n * CN + c)) * HW;

    float w0[9], w1[9];
    #pragma unroll
    for (int k = 0; k < 9; k++) { w0[k] = __ldg(dww + c * 9 + k); w1[k] = __ldg(dww + (c + 64) * 9 + k); }
    float b0 = __ldg(dwb + c), b1 = __ldg(dwb + c + 64);

    // prologue: rows strip0-1, strip0 (2 rows x 2ch x 64 float4 = 256 float4)
    {
        int ch = t >> 7;
        int ri = (t >> 6) & 1;
        int c4 = t & 63;
        int ar = strip0 - 1 + ri;
        float4 v = make_float4(0.f, 0.f, 0.f, 0.f);
        if ((unsigned)ar < 256u) {
            const float* src = ch ? u1 : u0;
            v = *(const float4*)(src + ar * 256 + c4 * 4);
        }
        *(float4*)(&s[ch][(ar + 1) & 7][c4 * 4]) = v;
    }

    float psum = 0.f;
    #pragma unroll 1
    for (int g = 0; g < 8; g++) {
        // load rows strip0+4g+1 .. +4 (4 rows x 2ch x 64 float4; 2 per thread)
        #pragma unroll
        for (int k = 0; k < 2; k++) {
            int idx = t + k * 256;
            int ch = idx >> 8;
            int ri = (idx >> 6) & 3;
            int c4 = idx & 63;
            int ar = strip0 + 4 * g + 1 + ri;
            float4 v = make_float4(0.f, 0.f, 0.f, 0.f);
            if ((unsigned)ar < 256u) {
                const float* src = ch ? u1 : u0;
                v = *(const float4*)(src + ar * 256 + c4 * 4);
            }
            *(float4*)(&s[ch][(ar + 1) & 7][c4 * 4]) = v;
        }
        __syncthreads();
        int r = strip0 + 4 * g + ty;      // output row
        float a0 = b0, a1 = b0, a2 = b0, a3 = b0;
        float d0 = b1, d1 = b1, d2 = b1, d3 = b1;
        #pragma unroll
        for (int ky = 0; ky < 3; ky++) {
            int slot = (r + ky) & 7;      // input row r-1+ky
            const float* row0 = &s[0][slot][0];
            const float* row1 = &s[1][slot][0];
            float4 cv = *(const float4*)(row0 + tx * 4);
            float lv = tx ? row0[tx * 4 - 1] : 0.f;
            float rv = (tx != 63) ? row0[tx * 4 + 4] : 0.f;
            a0 += w0[ky*3]*lv   + w0[ky*3+1]*cv.x + w0[ky*3+2]*cv.y;
            a1 += w0[ky*3]*cv.x + w0[ky*3+1]*cv.y + w0[ky*3+2]*cv.z;
            a2 += w0[ky*3]*cv.y + w0[ky*3+1]*cv.z + w0[ky*3+2]*cv.w;
            a3 += w0[ky*3]*cv.z + w0[ky*3+1]*cv.w + w0[ky*3+2]*rv;
            float4 dv = *(const float4*)(row1 + tx * 4);
            float lw = tx ? row1[tx * 4 - 1] : 0.f;
            float rw = (tx != 63) ? row1[tx * 4 + 4] : 0.f;
            d0 += w1[ky*3]*lw   + w1[ky*3+1]*dv.x + w1[ky*3+2]*dv.y;
            d1 += w1[ky*3]*dv.x + w1[ky*3+1]*dv.y + w1[ky*3+2]*dv.z;
            d2 += w1[ky*3]*dv.y + w1[ky*3+1]*dv.z + w1[ky*3+2]*dv.w;
            d3 += w1[ky*3]*dv.z + w1[ky*3+1]*dv.w + w1[ky*3+2]*rw;
        }
        float g0 = a0 * d0, g1 = a1 * d1, g2 = a2 * d2, g3 = a3 * d3;
        *(float4*)(gp + r * 256 + tx * 4) = make_float4(g0, g1, g2, g3);
        psum += (g0 + g1) + (g2 + g3);
        __syncthreads();                  // protect ring before next load
    }
    for (int o = 16; o; o >>= 1) psum += __shfl_down_sync(0xffffffffu, psum, o);
    if ((t & 31) == 0) red[t >> 5] = psum;
    __syncthreads();
    if (t < 8) {
        float v = red[t];
        v += __shfl_down_sync(0xffu, v, 4);
        v += __shfl_down_sync(0xffu, v, 2);
        v += __shfl_down_sync(0xffu, v, 1);
        if (t == 0) atomicAdd(&g_pool[nc], v);
    }
}

// ---------------- K5: SCA sigmoid, fold scale into pw2 weights -------------------
__global__ void k_sca(const float* __restrict__ scaw, const float* __restrict__ scab,
                      const float* __restrict__ pw2w) {
    int n = blockIdx.x, o = threadIdx.x;   // 64 threads
    __shared__ float pm[CN], sc[CN];
    pm[o] = g_pool[n * CN + o] * (1.f / HW);
    __syncthreads();
    float acc = scab[o];
    for (int i = 0; i < CN; i++) acc += scaw[o * CN + i] * pm[i];
    sc[o] = 1.f / (1.f + expf(-acc));
    __syncthreads();
    for (int i = 0; i < CN; i++) {
        float we = pw2w[o * CN + i] * sc[i];
        g_w2d[(n * CN + i) * CN + o] = make_float2(we, we);
    }
}

// ---------------- K6: pw2 GEMM + residual + LN2 stats accumulation ---------------
__global__ void __launch_bounds__(512) k_pw2(const float* __restrict__ x,
                                             const float* __restrict__ pw2b,
                                             const float* __restrict__ beta1) {
    extern __shared__ float sm[];
    float*  gs = sm;                       // [64][128]
    float2* wd = (float2*)(sm + CN * 128); // [64][64]
    __shared__ float s_sum[CN], s_sq[CN];
    int n = blockIdx.y;
    int p0 = blockIdx.x * 128;
    int t = threadIdx.x;
    if (t < CN) { s_sum[t] = 0.f; s_sq[t] = 0.f; }
    {
        const float4* src = (const float4*)(g_g + (size_t)n * CN * HW);
        float4* dst = (float4*)gs;
        #pragma unroll
        for (int k = 0; k < 4; k++) {
            int idx = t + k * 512;
            int i = idx >> 5, px4 = idx & 31;
            dst[idx] = src[(size_t)i * (HW / 4) + (p0 >> 2) + px4];
        }
        const float4* wsrc = (const float4*)(g_w2d + n * CN * CN);
        float4* wdst = (float4*)wd;
        #pragma unroll
        for (int k = 0; k < 4; k++) wdst[t + k * 512] = wsrc[t + k * 512];
    }
    __syncthreads();
    int o0 = (t >> 5) * 4;
    int px = (t & 31) * 4;
    unsigned long long acc[8];
    #pragma unroll
    for (int c = 0; c < 8; c++) acc[c] = 0ull;
    #pragma unroll 8
    for (int i = 0; i < CN; i++) {
        const ulonglong2* wr = (const ulonglong2*)(wd + i * CN + o0);
        ulonglong2 w0 = wr[0], w1 = wr[1];
        ulonglong2 xv = *(const ulonglong2*)(gs + i * 128 + px);
        unsigned long long xp0 = xv.x, xp1 = xv.y;
        acc[0] = ffma2(w0.x, xp0, acc[0]); acc[1] = ffma2(w0.x, xp1, acc[1]);
        acc[2] = ffma2(w0.y, xp0, acc[2]); acc[3] = ffma2(w0.y, xp1, acc[3]);
        acc[4] = ffma2(w1.x, xp0, acc[4]); acc[5] = ffma2(w1.x, xp1, acc[5]);
        acc[6] = ffma2(w1.y, xp0, acc[6]); acc[7] = ffma2(w1.y, xp1, acc[7]);
    }
    #pragma unroll
    for (int c = 0; c < 4; c++) {
        int o = o0 + c;
        float b = pw2b[o], bt = beta1[o];
        float2 lo = unpack2(acc[2 * c]), hi = unpack2(acc[2 * c + 1]);
        size_t off = ((size_t)(n * CN + o)) * HW + p0 + px;
        float4 xv = *(const float4*)(x + off);
        float4 r;
        r.x = xv.x + bt * (lo.x + b);
        r.y = xv.y + bt * (lo.y + b);
        r.z = xv.z + bt * (hi.x + b);
        r.w = xv.w + bt * (hi.y + b);
        *(float4*)(g_x1 + off) = r;
        float ls = r.x + r.y + r.z + r.w;
        float lq = r.x * r.x + r.y * r.y + r.z * r.z + r.w * r.w;
        for (int of = 16; of; of >>= 1) {
            ls += __shfl_down_sync(0xffffffffu, ls, of);
            lq += __shfl_down_sync(0xffffffffu, lq, of);
        }
        if ((t & 31) == 0) { atomicAdd(&s_sum[o], ls); atomicAdd(&s_sq[o], lq); }
    }
    __syncthreads();
    if (t < CN) {
        atomicAdd(&g_sum2[n * CN + t],   s_sum[t]);
        atomicAdd(&g_sumsq2[n * CN + t], s_sq[t]);
    }
}

// ---------------- K7: LN2 finalize + fold into pw3; duplicate pw4 ----------------
__global__ void k_prep3(const float* __restrict__ ln2w, const float* __restrict__ ln2b,
                        const float* __restrict__ pw3w, const float* __restrict__ pw3b,
                        const float* __restrict__ pw4w) {
    int n = blockIdx.x, o = threadIdx.x;   // 128 threads
    __shared__ float m2[CN], r2[CN];
    if (o < CN) {
        float m = g_sum2[n * CN + o] * (1.f / HW);
        float var = g_sumsq2[n * CN + o] * (1.f / HW) - m * m;
        m2[o] = m;
        r2[o] = rsqrtf(var + EPSV);
    }
    __syncthreads();
    float bias = pw3b[o];
    for (int i = 0; i < CN; i++) {
        float a  = r2[i] * ln2w[i];
        float c0 = ln2b[i] - m2[i] * a;
        float w  = pw3w[o * CN + i];
        bias += w * c0;
        float we = w * a;
        g_w3d[(n * CN + i) * C2 + o] = make_float2(we, we);
    }
    g_b3e[n * C2 + o] = bias;
    if (n == 0 && o < CN) {
        for (int i = 0; i < CN; i++) {
            float w = pw4w[o * CN + i];
            g_w4d[i * CN + o] = make_float2(w, w);
        }
    }
}

// ---------------- K8: pw3 GEMM -> gate -> pw4 GEMM -> residual -> out ------------
__global__ void __launch_bounds__(512) k_final(const float* __restrict__ pw4b,
                                               const float* __restrict__ beta2,
                                               float* __restrict__ out) {
    extern __shared__ float sm[];
    float*  xs = sm;                                   // 8192 floats (x1 tile)
    float2* w3 = (float2*)(sm + 8192);                 // 8192 float2
    float*  us = sm + 8192 + 16384;                    // 16384 floats
    float2* w4 = (float2*)(sm + 8192 + 16384 + 16384); // 4096 float2
    int n = blockIdx.y;
    int p0 = blockIdx.x * 128;
    int t = threadIdx.x;
    {
        const float4* src = (const float4*)(g_x1 + (size_t)n * CN * HW);
        float4* dst = (float4*)xs;
        #pragma unroll
        for (int k = 0; k < 4; k++) {
            int idx = t + k * 512;
            int i = idx >> 5, px4 = idx & 31;
            dst[idx] = src[(size_t)i * (HW / 4) + (p0 >> 2) + px4];
        }
        const float4* w3s = (const float4*)(g_w3d + n * CN * C2);
        float4* w3dst = (float4*)w3;
        #pragma unroll
        for (int k = 0; k < 8; k++) w3dst[t + k * 512] = w3s[t + k * 512];
        const float4* w4s = (const float4*)g_w4d;
        float4* w4dst = (float4*)w4;
        #pragma unroll
        for (int k = 0; k < 4; k++) w4dst[t + k * 512] = w4s[t + k * 512];
    }
    __syncthreads();
    int px = (t & 31) * 4;
    // Phase A: pw3 (LN2 folded) -> us
    {
        int o0 = (t >> 5) * 8;
        unsigned long long acc[16];
        #pragma unroll
        for (int c = 0; c < 16; c++) acc[c] = 0ull;
        #pragma unroll 8
        for (int i = 0; i < CN; i++) {
            const ulonglong2* wr = (const ulonglong2*)(w3 + i * C2 + o0);
            ulonglong2 w0 = wr[0], w1 = wr[1], w2 = wr[2], wv3 = wr[3];
            ulonglong2 xv = *(const ulonglong2*)(xs + i * 128 + px);
            unsigned long long xp0 = xv.x, xp1 = xv.y;
            acc[0]  = ffma2(w0.x, xp0, acc[0]);  acc[1]  = ffma2(w0.x, xp1, acc[1]);
            acc[2]  = ffma2(w0.y, xp0, acc[2]);  acc[3]  = ffma2(w0.y, xp1, acc[3]);
            acc[4]  = ffma2(w1.x, xp0, acc[4]);  acc[5]  = ffma2(w1.x, xp1, acc[5]);
            acc[6]  = ffma2(w1.y, xp0, acc[6]);  acc[7]  = ffma2(w1.y, xp1, acc[7]);
            acc[8]  = ffma2(w2.x, xp0, acc[8]);  acc[9]  = ffma2(w2.x, xp1, acc[9]);
            acc[10] = ffma2(w2.y, xp0, acc[10]); acc[11] = ffma2(w2.y, xp1, acc[11]);
            acc[12] = ffma2(wv3.x, xp0, acc[12]); acc[13] = ffma2(wv3.x, xp1, acc[13]);
            acc[14] = ffma2(wv3.y, xp0, acc[14]); acc[15] = ffma2(wv3.y, xp1, acc[15]);
        }
        #pragma unroll
        for (int c = 0; c < 8; c++) {
            float b = g_b3e[n * C2 + o0 + c];
            float2 lo = unpack2(acc[2 * c]), hi = unpack2(acc[2 * c + 1]);
            *(float4*)(us + (o0 + c) * 128 + px) = make_float4(lo.x + b, lo.y + b, hi.x + b, hi.y + b);
        }
    }
    __syncthreads();
    // Gate in place: us[c] *= us[c+64]  (c < 64)
    {
        float4* us4 = (float4*)us;
        #pragma unroll
        for (int k = 0; k < 4; k++) {
            int idx = t + k * 512;          // 2048 float4s over c<64
            int c = idx >> 5, q = idx & 31;
            float4 a = us4[c * 32 + q];
            float4 b = us4[(c + 64) * 32 + q];
            us4[c * 32 + q] = make_float4(a.x * b.x, a.y * b.y, a.z * b.z, a.w * b.w);
        }
    }
    __syncthreads();
    // Phase B: pw4 + residual + store
    {
        int o0 = (t >> 5) * 4;
        unsigned long long acc[8];
        #pragma unroll
        for (int c = 0; c < 8; c++) acc[c] = 0ull;
        #pragma unroll 8
        for (int i = 0; i < CN; i++) {
            const ulonglong2* wr = (const ulonglong2*)(w4 + i * CN + o0);
            ulonglong2 w0 = wr[0], w1 = wr[1];
            ulonglong2 xv = *(const ulonglong2*)(us + i * 128 + px);
            unsigned long long xp0 = xv.x, xp1 = xv.y;
            acc[0] = ffma2(w0.x, xp0, acc[0]); acc[1] = ffma2(w0.x, xp1, acc[1]);
            acc[2] = ffma2(w0.y, xp0, acc[2]); acc[3] = ffma2(w0.y, xp1, acc[3]);
            acc[4] = ffma2(w1.x, xp0, acc[4]); acc[5] = ffma2(w1.x, xp1, acc[5]);
            acc[6] = ffma2(w1.y, xp0, acc[6]); acc[7] = ffma2(w1.y, xp1, acc[7]);
        }
        #pragma unroll
        for (int c = 0; c < 4; c++) {
            int o = o0 + c;
            float b = pw4b[o], bt = beta2[o];
            float2 lo = unpack2(acc[2 * c]), hi = unpack2(acc[2 * c + 1]);
            float4 x1v = *(const float4*)(xs + o * 128 + px);
            float4 r;
            r.x = x1v.x + bt * (lo.x + b);
            r.y = x1v.y + bt * (lo.y + b);
            r.z = x1v.z + bt * (hi.x + b);
            r.w = x1v.w + bt * (hi.y + b);
            *(float4*)(out + ((size_t)(n * CN + o)) * HW + p0 + px) = r;
        }
    }
}

// ---------------- host ------------------------------------------------------------
extern "C" void kernel_launch(void* const* d_in, const int* in_sizes, int n_in,
                              void* d_out, int out_size) {
    const float* x     = (const float*)d_in[0];
    const float* ln1w  = (const float*)d_in[1];
    const float* ln1b  = (const float*)d_in[2];
    const float* pw1w  = (const float*)d_in[3];
    const float* pw1b  = (const float*)d_in[4];
    const float* dww   = (const float*)d_in[5];
    const float* dwb   = (const float*)d_in[6];
    const float* scaw  = (const float*)d_in[7];
    const float* scab  = (const float*)d_in[8];
    const float* pw2w  = (const float*)d_in[9];
    const float* pw2b  = (const float*)d_in[10];
    const float* ln2w  = (const float*)d_in[11];
    const float* ln2b  = (const float*)d_in[12];
    const float* pw3w  = (const float*)d_in[13];
    const float* pw3b  = (const float*)d_in[14];
    const float* pw4w  = (const float*)d_in[15];
    const float* pw4b  = (const float*)d_in[16];
    const float* beta1 = (const float*)d_in[17];
    const float* beta2 = (const float*)d_in[18];

    cudaFuncSetAttribute(k_pw1,   cudaFuncAttributeMaxDynamicSharedMemorySize, 96 * 1024);
    cudaFuncSetAttribute(k_pw2,   cudaFuncAttributeMaxDynamicSharedMemorySize, 64 * 1024);
    cudaFuncSetAttribute(k_final, cudaFuncAttributeMaxDynamicSharedMemorySize, 192 * 1024);

    k_stats1<<<NB * CN, 256>>>(x);
    k_prep1<<<NB, C2>>>(ln1w, ln1b, pw1w, pw1b);
    k_pw1<<<dim3(512, NB), 512, 96 * 1024>>>(x);
    k_dwgate<<<dim3(NB * CN, 8), 256>>>(dww, dwb);
    k_sca<<<NB, CN>>>(scaw, scab, pw2w);
    k_pw2<<<dim3(512, NB), 512, 64 * 1024>>>(x, pw2b, beta1);
    k_prep3<<<NB, C2>>>(ln2w, ln2b, pw3w, pw3b, pw4w);
    k_final<<<dim3(512, NB), 512, 192 * 1024>>>(pw4b, beta2, (float*)d_out);
}

// round 5
// speedup vs baseline: 1.1447x; 1.0058x over previous
#include <cuda_runtime.h>

#define HW 65536
#define CN 64
#define C2 128
#define NB 8
#define EPSV 1e-6f

// ---------------- scratch (device globals; no cudaMalloc allowed) ----------------
__device__ float  g_u [(size_t)NB*C2*HW];   // pw1 output (pre-dwconv), 268MB
__device__ float  g_g [(size_t)NB*CN*HW];   // gated (pre-SCA-scale), 134MB
__device__ float  g_x1[(size_t)NB*CN*HW];   // first residual output, 134MB
__device__ float  g_mean1[NB*CN];
__device__ float  g_rstd1[NB*CN];
__device__ float  g_pool [NB*CN];
__device__ float  g_sum2 [NB*CN];
__device__ float  g_sumsq2[NB*CN];
__device__ float2 g_w1d[NB*CN*C2];          // LN1-folded pw1 weights, duplicated (w,w), [n][i][o]
__device__ float  g_b1e[NB*C2];
__device__ float2 g_w2d[NB*CN*CN];          // SCA-scale-folded pw2 weights, [n][i][o]
__device__ float2 g_w3d[NB*CN*C2];          // LN2-folded pw3 weights, [n][i][o]
__device__ float  g_b3e[NB*C2];
__device__ float2 g_w4d[CN*CN];             // pw4 duplicated, [i][o]

// ---------------- packed fp32x2 FMA (2 MACs/instruction on sm_103a) --------------
__device__ __forceinline__ unsigned long long ffma2(unsigned long long a,
                                                    unsigned long long b,
                                                    unsigned long long c) {
    unsigned long long d;
    asm("fma.rn.f32x2 %0, %1, %2, %3;" : "=l"(d) : "l"(a), "l"(b), "l"(c));
    return d;
}
__device__ __forceinline__ float2 unpack2(unsigned long long v) {
    float2 r;
    r.x = __uint_as_float((unsigned)(v & 0xffffffffull));
    r.y = __uint_as_float((unsigned)(v >> 32));
    return r;
}

// ---------------- K1: LN1 stats over HW per (n,c) --------------------------------
__global__ void k_stats1(const float* __restrict__ x) {
    int nc = blockIdx.x;
    const float4* p = (const float4*)(x + (size_t)nc * HW);
    float s = 0.f, q = 0.f;
    for (int j = threadIdx.x; j < HW / 4; j += 256) {
        float4 v = p[j];
        s += v.x + v.y + v.z + v.w;
        q += v.x * v.x + v.y * v.y + v.z * v.z + v.w * v.w;
    }
    __shared__ float rs[8], rq[8];
    for (int o = 16; o; o >>= 1) {
        s += __shfl_down_sync(0xffffffffu, s, o);
        q += __shfl_down_sync(0xffffffffu, q, o);
    }
    if ((threadIdx.x & 31) == 0) { rs[threadIdx.x >> 5] = s; rq[threadIdx.x >> 5] = q; }
    __syncthreads();
    if (threadIdx.x == 0) {
        float S = 0.f, Q = 0.f;
        for (int i = 0; i < 8; i++) { S += rs[i]; Q += rq[i]; }
        float m = S * (1.f / HW);
        float var = Q * (1.f / HW) - m * m;
        g_mean1[nc] = m;
        g_rstd1[nc] = rsqrtf(var + EPSV);
    }
}

// ---------------- K2: fold LN1 into pw1, zero accumulators -----------------------
__global__ void k_prep1(const float* __restrict__ ln1w, const float* __restrict__ ln1b,
                        const float* __restrict__ pw1w, const float* __restrict__ pw1b) {
    int n = blockIdx.x, o = threadIdx.x;   // 128 threads
    float bias = pw1b[o];
    for (int i = 0; i < CN; i++) {
        float a  = g_rstd1[n * CN + i] * ln1w[i];
        float c0 = ln1b[i] - g_mean1[n * CN + i] * a;
        float w  = pw1w[o * CN + i];
        bias += w * c0;
        float we = w * a;
        g_w1d[(n * CN + i) * C2 + o] = make_float2(we, we);
    }
    g_b1e[n * C2 + o] = bias;
    int idx = n * C2 + o;
    if (idx < NB * CN) { g_pool[idx] = 0.f; g_sum2[idx] = 0.f; g_sumsq2[idx] = 0.f; }
}

// ---------------- K3: pw1 GEMM (LN folded), u = W1eff @ x + b1eff ----------------
__global__ void __launch_bounds__(512) k_pw1(const float* __restrict__ x) {
    extern __shared__ float sm[];
    float*  xs = sm;                       // [64][128]
    float2* wd = (float2*)(sm + CN * 128); // [64][128] duplicated
    int n = blockIdx.y;
    int p0 = blockIdx.x * 128;
    int t = threadIdx.x;
    {
        const float4* src = (const float4*)(x + (size_t)n * CN * HW);
        float4* dst = (float4*)xs;
        #pragma unroll
        for (int k = 0; k < 4; k++) {
            int idx = t + k * 512;
            int i = idx >> 5, px4 = idx & 31;
            dst[idx] = src[(size_t)i * (HW / 4) + (p0 >> 2) + px4];
        }
        const float4* wsrc = (const float4*)(g_w1d + n * CN * C2);
        float4* wdst = (float4*)wd;
        #pragma unroll
        for (int k = 0; k < 8; k++) wdst[t + k * 512] = wsrc[t + k * 512];
    }
    __syncthreads();
    int o0 = (t >> 5) * 8;
    int px = (t & 31) * 4;
    unsigned long long acc[16];
    #pragma unroll
    for (int c = 0; c < 16; c++) acc[c] = 0ull;
    #pragma unroll 8
    for (int i = 0; i < CN; i++) {
        const ulonglong2* wr = (const ulonglong2*)(wd + i * C2 + o0);
        ulonglong2 w0 = wr[0], w1 = wr[1], w2 = wr[2], w3 = wr[3];
        ulonglong2 xv = *(const ulonglong2*)(xs + i * 128 + px);
        unsigned long long xp0 = xv.x, xp1 = xv.y;
        acc[0]  = ffma2(w0.x, xp0, acc[0]);  acc[1]  = ffma2(w0.x, xp1, acc[1]);
        acc[2]  = ffma2(w0.y, xp0, acc[2]);  acc[3]  = ffma2(w0.y, xp1, acc[3]);
        acc[4]  = ffma2(w1.x, xp0, acc[4]);  acc[5]  = ffma2(w1.x, xp1, acc[5]);
        acc[6]  = ffma2(w1.y, xp0, acc[6]);  acc[7]  = ffma2(w1.y, xp1, acc[7]);
        acc[8]  = ffma2(w2.x, xp0, acc[8]);  acc[9]  = ffma2(w2.x, xp1, acc[9]);
        acc[10] = ffma2(w2.y, xp0, acc[10]); acc[11] = ffma2(w2.y, xp1, acc[11]);
        acc[12] = ffma2(w3.x, xp0, acc[12]); acc[13] = ffma2(w3.x, xp1, acc[13]);
        acc[14] = ffma2(w3.y, xp0, acc[14]); acc[15] = ffma2(w3.y, xp1, acc[15]);
    }
    #pragma unroll
    for (int c = 0; c < 8; c++) {
        float b = g_b1e[n * C2 + o0 + c];
        float2 lo = unpack2(acc[2 * c]), hi = unpack2(acc[2 * c + 1]);
        float4 out = make_float4(lo.x + b, lo.y + b, hi.x + b, hi.y + b);
        *(float4*)(g_u + ((size_t)(n * C2 + o0 + c)) * HW + p0 + px) = out;
    }
}

// ---------------- K4: depthwise 3x3 + gate + SCA pool partials (row-streaming) ---
// One block = one (n, channel-pair) x 32-row strip. 256 threads = 64 col-quads x 4 rows.
// 8-slot smem row ring per channel; 4 fresh rows loaded per iteration.
__global__ void __launch_bounds__(256) k_dwgate(const float* __restrict__ dww,
                                                const float* __restrict__ dwb) {
    __shared__ float s[2][8][256];
    __shared__ float red[8];
    int t = threadIdx.x;
    int tx = t & 63, ty = t >> 6;
    int nc = blockIdx.x;                  // n*64 + c
    int n = nc >> 6, c = nc & 63;
    int strip0 = blockIdx.y * 32;

    const float* u0 = g_u + ((size_t)(n * C2 + c)) * HW;
    const float* u1 = g_u + ((size_t)(n * C2 + c + 64)) * HW;
    float*       gp = g_g + ((size_t)(n * CN + c)) * HW;

    float w0[9], w1[9];
    #pragma unroll
    for (int k = 0; k < 9; k++) { w0[k] = __ldg(dww + c * 9 + k); w1[k] = __ldg(dww + (c + 64) * 9 + k); }
    float b0 = __ldg(dwb + c), b1 = __ldg(dwb + c + 64);

    // prologue: rows strip0-1, strip0 (2 rows x 2ch x 64 float4 = 256 float4)
    {
        int ch = t >> 7;
        int ri = (t >> 6) & 1;
        int c4 = t & 63;
        int ar = strip0 - 1 + ri;
        float4 v = make_float4(0.f, 0.f, 0.f, 0.f);
        if ((unsigned)ar < 256u) {
            const float* src = ch ? u1 : u0;
            v = *(const float4*)(src + ar * 256 + c4 * 4);
        }
        *(float4*)(&s[ch][(ar + 1) & 7][c4 * 4]) = v;
    }

    float psum = 0.f;
    #pragma unroll 1
    for (int g = 0; g < 8; g++) {
        // load rows strip0+4g+1 .. +4 (4 rows x 2ch x 64 float4; 2 per thread)
        #pragma unroll
        for (int k = 0; k < 2; k++) {
            int idx = t + k * 256;
            int ch = idx >> 8;
            int ri = (idx >> 6) & 3;
            int c4 = idx & 63;
            int ar = strip0 + 4 * g + 1 + ri;
            float4 v = make_float4(0.f, 0.f, 0.f, 0.f);
            if ((unsigned)ar < 256u) {
                const float* src = ch ? u1 : u0;
                v = *(const float4*)(src + ar * 256 + c4 * 4);
            }
            *(float4*)(&s[ch][(ar + 1) & 7][c4 * 4]) = v;
        }
        __syncthreads();
        int r = strip0 + 4 * g + ty;      // output row
        float a0 = b0, a1 = b0, a2 = b0, a3 = b0;
        float d0 = b1, d1 = b1, d2 = b1, d3 = b1;
        #pragma unroll
        for (int ky = 0; ky < 3; ky++) {
            int slot = (r + ky) & 7;      // input row r-1+ky
            const float* row0 = &s[0][slot][0];
            const float* row1 = &s[1][slot][0];
            float4 cv = *(const float4*)(row0 + tx * 4);
            float lv = tx ? row0[tx * 4 - 1] : 0.f;
            float rv = (tx != 63) ? row0[tx * 4 + 4] : 0.f;
            a0 += w0[ky*3]*lv   + w0[ky*3+1]*cv.x + w0[ky*3+2]*cv.y;
            a1 += w0[ky*3]*cv.x + w0[ky*3+1]*cv.y + w0[ky*3+2]*cv.z;
            a2 += w0[ky*3]*cv.y + w0[ky*3+1]*cv.z + w0[ky*3+2]*cv.w;
            a3 += w0[ky*3]*cv.z + w0[ky*3+1]*cv.w + w0[ky*3+2]*rv;
            float4 dv = *(const float4*)(row1 + tx * 4);
            float lw = tx ? row1[tx * 4 - 1] : 0.f;
            float rw = (tx != 63) ? row1[tx * 4 + 4] : 0.f;
            d0 += w1[ky*3]*lw   + w1[ky*3+1]*dv.x + w1[ky*3+2]*dv.y;
            d1 += w1[ky*3]*dv.x + w1[ky*3+1]*dv.y + w1[ky*3+2]*dv.z;
            d2 += w1[ky*3]*dv.y + w1[ky*3+1]*dv.z + w1[ky*3+2]*dv.w;
            d3 += w1[ky*3]*dv.z + w1[ky*3+1]*dv.w + w1[ky*3+2]*rw;
        }
        float g0 = a0 * d0, g1 = a1 * d1, g2 = a2 * d2, g3 = a3 * d3;
        *(float4*)(gp + r * 256 + tx * 4) = make_float4(g0, g1, g2, g3);
        psum += (g0 + g1) + (g2 + g3);
        __syncthreads();                  // protect ring before next load
    }
    for (int o = 16; o; o >>= 1) psum += __shfl_down_sync(0xffffffffu, psum, o);
    if ((t & 31) == 0) red[t >> 5] = psum;
    __syncthreads();
    if (t < 8) {
        float v = red[t];
        v += __shfl_down_sync(0xffu, v, 4);
        v += __shfl_down_sync(0xffu, v, 2);
        v += __shfl_down_sync(0xffu, v, 1);
        if (t == 0) atomicAdd(&g_pool[nc], v);
    }
}

// ---------------- K5: SCA sigmoid, fold scale into pw2 weights -------------------
__global__ void k_sca(const float* __restrict__ scaw, const float* __restrict__ scab,
                      const float* __restrict__ pw2w) {
    int n = blockIdx.x, o = threadIdx.x;   // 64 threads
    __shared__ float pm[CN], sc[CN];
    pm[o] = g_pool[n * CN + o] * (1.f / HW);
    __syncthreads();
    float acc = scab[o];
    for (int i = 0; i < CN; i++) acc += scaw[o * CN + i] * pm[i];
    sc[o] = 1.f / (1.f + expf(-acc));
    __syncthreads();
    for (int i = 0; i < CN; i++) {
        float we = pw2w[o * CN + i] * sc[i];
        g_w2d[(n * CN + i) * CN + o] = make_float2(we, we);
    }
}

// ---------------- K6: pw2 GEMM + residual + LN2 stats accumulation ---------------
__global__ void __launch_bounds__(512) k_pw2(const float* __restrict__ x,
                                             const float* __restrict__ pw2b,
                                             const float* __restrict__ beta1) {
    extern __shared__ float sm[];
    float*  gs = sm;                       // [64][128]
    float2* wd = (float2*)(sm + CN * 128); // [64][64]
    __shared__ float s_sum[CN], s_sq[CN];
    int n = blockIdx.y;
    int p0 = blockIdx.x * 128;
    int t = threadIdx.x;
    if (t < CN) { s_sum[t] = 0.f; s_sq[t] = 0.f; }
    {
        const float4* src = (const float4*)(g_g + (size_t)n * CN * HW);
        float4* dst = (float4*)gs;
        #pragma unroll
        for (int k = 0; k < 4; k++) {
            int idx = t + k * 512;
            int i = idx >> 5, px4 = idx & 31;
            dst[idx] = src[(size_t)i * (HW / 4) + (p0 >> 2) + px4];
        }
        const float4* wsrc = (const float4*)(g_w2d + n * CN * CN);
        float4* wdst = (float4*)wd;
        #pragma unroll
        for (int k = 0; k < 4; k++) wdst[t + k * 512] = wsrc[t + k * 512];
    }
    __syncthreads();
    int o0 = (t >> 5) * 4;
    int px = (t & 31) * 4;
    unsigned long long acc[8];
    #pragma unroll
    for (int c = 0; c < 8; c++) acc[c] = 0ull;
    #pragma unroll 8
    for (int i = 0; i < CN; i++) {
        const ulonglong2* wr = (const ulonglong2*)(wd + i * CN + o0);
        ulonglong2 w0 = wr[0], w1 = wr[1];
        ulonglong2 xv = *(const ulonglong2*)(gs + i * 128 + px);
        unsigned long long xp0 = xv.x, xp1 = xv.y;
        acc[0] = ffma2(w0.x, xp0, acc[0]); acc[1] = ffma2(w0.x, xp1, acc[1]);
        acc[2] = ffma2(w0.y, xp0, acc[2]); acc[3] = ffma2(w0.y, xp1, acc[3]);
        acc[4] = ffma2(w1.x, xp0, acc[4]); acc[5] = ffma2(w1.x, xp1, acc[5]);
        acc[6] = ffma2(w1.y, xp0, acc[6]); acc[7] = ffma2(w1.y, xp1, acc[7]);
    }
    #pragma unroll
    for (int c = 0; c < 4; c++) {
        int o = o0 + c;
        float b = pw2b[o], bt = beta1[o];
        float2 lo = unpack2(acc[2 * c]), hi = unpack2(acc[2 * c + 1]);
        size_t off = ((size_t)(n * CN + o)) * HW + p0 + px;
        float4 xv = *(const float4*)(x + off);
        float4 r;
        r.x = xv.x + bt * (lo.x + b);
        r.y = xv.y + bt * (lo.y + b);
        r.z = xv.z + bt * (hi.x + b);
        r.w = xv.w + bt * (hi.y + b);
        *(float4*)(g_x1 + off) = r;
        float ls = r.x + r.y + r.z + r.w;
        float lq = r.x * r.x + r.y * r.y + r.z * r.z + r.w * r.w;
        for (int of = 16; of; of >>= 1) {
            ls += __shfl_down_sync(0xffffffffu, ls, of);
            lq += __shfl_down_sync(0xffffffffu, lq, of);
        }
        if ((t & 31) == 0) { atomicAdd(&s_sum[o], ls); atomicAdd(&s_sq[o], lq); }
    }
    __syncthreads();
    if (t < CN) {
        atomicAdd(&g_sum2[n * CN + t],   s_sum[t]);
        atomicAdd(&g_sumsq2[n * CN + t], s_sq[t]);
    }
}

// ---------------- K7: LN2 finalize + fold into pw3; duplicate pw4 ----------------
__global__ void k_prep3(const float* __restrict__ ln2w, const float* __restrict__ ln2b,
                        const float* __restrict__ pw3w, const float* __restrict__ pw3b,
                        const float* __restrict__ pw4w) {
    int n = blockIdx.x, o = threadIdx.x;   // 128 threads
    __shared__ float m2[CN], r2[CN];
    if (o < CN) {
        float m = g_sum2[n * CN + o] * (1.f / HW);
        float var = g_sumsq2[n * CN + o] * (1.f / HW) - m * m;
        m2[o] = m;
        r2[o] = rsqrtf(var + EPSV);
    }
    __syncthreads();
    float bias = pw3b[o];
    for (int i = 0; i < CN; i++) {
        float a  = r2[i] * ln2w[i];
        float c0 = ln2b[i] - m2[i] * a;
        float w  = pw3w[o * CN + i];
        bias += w * c0;
        float we = w * a;
        g_w3d[(n * CN + i) * C2 + o] = make_float2(we, we);
    }
    g_b3e[n * C2 + o] = bias;
    if (n == 0 && o < CN) {
        for (int i = 0; i < CN; i++) {
            float w = pw4w[o * CN + i];
            g_w4d[i * CN + o] = make_float2(w, w);
        }
    }
}

// ---------------- K8: pw3 GEMM -> gate -> pw4 GEMM -> residual -> out ------------
__global__ void __launch_bounds__(512) k_final(const float* __restrict__ pw4b,
                                               const float* __restrict__ beta2,
                                               float* __restrict__ out) {
    extern __shared__ float sm[];
    float*  xs = sm;                                   // 8192 floats (x1 tile)
    float2* w3 = (float2*)(sm + 8192);                 // 8192 float2
    float*  us = sm + 8192 + 16384;                    // 16384 floats
    float2* w4 = (float2*)(sm + 8192 + 16384 + 16384); // 4096 float2
    int n = blockIdx.y;
    int p0 = blockIdx.x * 128;
    int t = threadIdx.x;
    {
        const float4* src = (const float4*)(g_x1 + (size_t)n * CN * HW);
        float4* dst = (float4*)xs;
        #pragma unroll
        for (int k = 0; k < 4; k++) {
            int idx = t + k * 512;
            int i = idx >> 5, px4 = idx & 31;
            dst[idx] = src[(size_t)i * (HW / 4) + (p0 >> 2) + px4];
        }
        const float4* w3s = (const float4*)(g_w3d + n * CN * C2);
        float4* w3dst = (float4*)w3;
        #pragma unroll
        for (int k = 0; k < 8; k++) w3dst[t + k * 512] = w3s[t + k * 512];
        const float4* w4s = (const float4*)g_w4d;
        float4* w4dst = (float4*)w4;
        #pragma unroll
        for (int k = 0; k < 4; k++) w4dst[t + k * 512] = w4s[t + k * 512];
    }
    __syncthreads();
    int px = (t & 31) * 4;
    // Phase A: pw3 (LN2 folded) -> us
    {
        int o0 = (t >> 5) * 8;
        unsigned long long acc[16];
        #pragma unroll
        for (int c = 0; c < 16; c++) acc[c] = 0ull;
        #pragma unroll 8
        for (int i = 0; i < CN; i++) {
            const ulonglong2* wr = (const ulonglong2*)(w3 + i * C2 + o0);
            ulonglong2 w0 = wr[0], w1 = wr[1], w2 = wr[2], wv3 = wr[3];
            ulonglong2 xv = *(const ulonglong2*)(xs + i * 128 + px);
            unsigned long long xp0 = xv.x, xp1 = xv.y;
            acc[0]  = ffma2(w0.x, xp0, acc[0]);  acc[1]  = ffma2(w0.x, xp1, acc[1]);
            acc[2]  = ffma2(w0.y, xp0, acc[2]);  acc[3]  = ffma2(w0.y, xp1, acc[3]);
            acc[4]  = ffma2(w1.x, xp0, acc[4]);  acc[5]  = ffma2(w1.x, xp1, acc[5]);
            acc[6]  = ffma2(w1.y, xp0, acc[6]);  acc[7]  = ffma2(w1.y, xp1, acc[7]);
            acc[8]  = ffma2(w2.x, xp0, acc[8]);  acc[9]  = ffma2(w2.x, xp1, acc[9]);
            acc[10] = ffma2(w2.y, xp0, acc[10]); acc[11] = ffma2(w2.y, xp1, acc[11]);
            acc[12] = ffma2(wv3.x, xp0, acc[12]); acc[13] = ffma2(wv3.x, xp1, acc[13]);
            acc[14] = ffma2(wv3.y, xp0, acc[14]); acc[15] = ffma2(wv3.y, xp1, acc[15]);
        }
        #pragma unroll
        for (int c = 0; c < 8; c++) {
            float b = g_b3e[n * C2 + o0 + c];
            float2 lo = unpack2(acc[2 * c]), hi = unpack2(acc[2 * c + 1]);
            *(float4*)(us + (o0 + c) * 128 + px) = make_float4(lo.x + b, lo.y + b, hi.x + b, hi.y + b);
        }
    }
    __syncthreads();
    // Gate in place: us[c] *= us[c+64]  (c < 64)
    {
        float4* us4 = (float4*)us;
        #pragma unroll
        for (int k = 0; k < 4; k++) {
            int idx = t + k * 512;          // 2048 float4s over c<64
            int c = idx >> 5, q = idx & 31;
            float4 a = us4[c * 32 + q];
            float4 b = us4[(c + 64) * 32 + q];
            us4[c * 32 + q] = make_float4(a.x * b.x, a.y * b.y, a.z * b.z, a.w * b.w);
        }
    }
    __syncthreads();
    // Phase B: pw4 + residual + store
    {
        int o0 = (t >> 5) * 4;
        unsigned long long acc[8];
        #pragma unroll
        for (int c = 0; c < 8; c++) acc[c] = 0ull;
        #pragma unroll 8
        for (int i = 0; i < CN; i++) {
            const ulonglong2* wr = (const ulonglong2*)(w4 + i * CN + o0);
            ulonglong2 w0 = wr[0], w1 = wr[1];
            ulonglong2 xv = *(const ulonglong2*)(us + i * 128 + px);
            unsigned long long xp0 = xv.x, xp1 = xv.y;
            acc[0] = ffma2(w0.x, xp0, acc[0]); acc[1] = ffma2(w0.x, xp1, acc[1]);
            acc[2] = ffma2(w0.y, xp0, acc[2]); acc[3] = ffma2(w0.y, xp1, acc[3]);
            acc[4] = ffma2(w1.x, xp0, acc[4]); acc[5] = ffma2(w1.x, xp1, acc[5]);
            acc[6] = ffma2(w1.y, xp0, acc[6]); acc[7] = ffma2(w1.y, xp1, acc[7]);
        }
        #pragma unroll
        for (int c = 0; c < 4; c++) {
            int o = o0 + c;
            float b = pw4b[o], bt = beta2[o];
            float2 lo = unpack2(acc[2 * c]), hi = unpack2(acc[2 * c + 1]);
            float4 x1v = *(const float4*)(xs + o * 128 + px);
            float4 r;
            r.x = x1v.x + bt * (lo.x + b);
            r.y = x1v.y + bt * (lo.y + b);
            r.z = x1v.z + bt * (hi.x + b);
            r.w = x1v.w + bt * (hi.y + b);
            *(float4*)(out + ((size_t)(n * CN + o)) * HW + p0 + px) = r;
        }
    }
}

// ---------------- host ------------------------------------------------------------
extern "C" void kernel_launch(void* const* d_in, const int* in_sizes, int n_in,
                              void* d_out, int out_size) {
    const float* x     = (const float*)d_in[0];
    const float* ln1w  = (const float*)d_in[1];
    const float* ln1b  = (const float*)d_in[2];
    const float* pw1w  = (const float*)d_in[3];
    const float* pw1b  = (const float*)d_in[4];
    const float* dww   = (const float*)d_in[5];
    const float* dwb   = (const float*)d_in[6];
    const float* scaw  = (const float*)d_in[7];
    const float* scab  = (const float*)d_in[8];
    const float* pw2w  = (const float*)d_in[9];
    const float* pw2b  = (const float*)d_in[10];
    const float* ln2w  = (const float*)d_in[11];
    const float* ln2b  = (const float*)d_in[12];
    const float* pw3w  = (const float*)d_in[13];
    const float* pw3b  = (const float*)d_in[14];
    const float* pw4w  = (const float*)d_in[15];
    const float* pw4b  = (const float*)d_in[16];
    const float* beta1 = (const float*)d_in[17];
    const float* beta2 = (const float*)d_in[18];

    cudaFuncSetAttribute(k_pw1,   cudaFuncAttributeMaxDynamicSharedMemorySize, 96 * 1024);
    cudaFuncSetAttribute(k_pw2,   cudaFuncAttributeMaxDynamicSharedMemorySize, 64 * 1024);
    cudaFuncSetAttribute(k_final, cudaFuncAttributeMaxDynamicSharedMemorySize, 192 * 1024);

    k_stats1<<<NB * CN, 256>>>(x);
    k_prep1<<<NB, C2>>>(ln1w, ln1b, pw1w, pw1b);
    k_pw1<<<dim3(512, NB), 512, 96 * 1024>>>(x);
    k_dwgate<<<dim3(NB * CN, 8), 256>>>(dww, dwb);
    k_sca<<<NB, CN>>>(scaw, scab, pw2w);
    k_pw2<<<dim3(512, NB), 512, 64 * 1024>>>(x, pw2b, beta1);
    k_prep3<<<NB, C2>>>(ln2w, ln2b, pw3w, pw3b, pw4w);
    k_final<<<dim3(512, NB), 512, 192 * 1024>>>(pw4b, beta2, (float*)d_out);
}

// round 7
// speedup vs baseline: 2.0214x; 1.7659x over previous
#include <cuda_runtime.h>
#include <cuda_bf16.h>
#include <cstdint>

#define HW 65536
#define CN 64
#define C2 128
#define NB 8
#define EPSV 1e-6f

__device__ float g_u [(size_t)NB*C2*HW];
__device__ float g_g [(size_t)NB*CN*HW];
__device__ float g_x1[(size_t)NB*CN*HW];
__device__ float g_mean1[NB*CN], g_rstd1[NB*CN], g_pool[NB*CN], g_sum2[NB*CN], g_sumsq2[NB*CN];
__device__ float g_b1e[NB*C2], g_b3e[NB*C2];
// packed bf16x2 weight tiles, [rows][32 words] (word j = channels 2j,2j+1)
__device__ __align__(16) unsigned g_w1p[NB*C2*32];
__device__ __align__(16) unsigned g_w2p[NB*CN*32];
__device__ __align__(16) unsigned g_w3p[NB*C2*32];
__device__ __align__(16) unsigned g_w4p[CN*32];

// res = {lo: a, hi: b}
#define CVT2(res,a,b) asm("cvt.rn.satfinite.bf16x2.f32 %0, %1, %2;" : "=r"(res) : "f"(b), "f"(a))

__device__ __forceinline__ void mma16816(float* d, const unsigned* a, unsigned b0, unsigned b1) {
    asm volatile("mma.sync.aligned.m16n8k16.row.col.f32.bf16.bf16.f32 "
        "{%0,%1,%2,%3}, {%4,%5,%6,%7}, {%8,%9}, {%0,%1,%2,%3};"
        : "+f"(d[0]), "+f"(d[1]), "+f"(d[2]), "+f"(d[3])
        : "r"(a[0]), "r"(a[1]), "r"(a[2]), "r"(a[3]), "r"(b0), "r"(b1));
}

// stage fp32 ch-major activations -> bf16 [128px][36 words] (72 bf16/row), 256 threads
__device__ __forceinline__ void stage_acts(unsigned* sa, const float* src, int n, int p0,
                                           int lane, int wid) {
    const float4* xa = (const float4*)(src + ((size_t)(n * CN + 2 * lane)) * HW) + (p0 >> 2);
    const float4* xb = xa + (HW >> 2);
    #pragma unroll
    for (int j = 0; j < 4; j++) {
        int px4 = wid * 4 + j;
        float4 a = xa[px4], b = xb[px4];
        int p = px4 * 4;
        unsigned v0, v1, v2, v3;
        CVT2(v0, a.x, b.x); CVT2(v1, a.y, b.y); CVT2(v2, a.z, b.z); CVT2(v3, a.w, b.w);
        sa[(p + 0) * 36 + lane] = v0;
        sa[(p + 1) * 36 + lane] = v1;
        sa[(p + 2) * 36 + lane] = v2;
        sa[(p + 3) * 36 + lane] = v3;
    }
}

__device__ __forceinline__ void copy_w(unsigned* sw, const unsigned* gw, int rows, int t) {
    int r = t >> 5, w = t & 31;
    for (; r < rows; r += 8) sw[r * 36 + w] = gw[r * 32 + w];
}

// warp GEMM: D[m-strip 16 x NT*8 px] += W @ B, K=64
template<int NT>
__device__ __forceinline__ void gemm_core(const unsigned* sw, const unsigned* sa,
                                          int ms, int ntb, int lane, float* d) {
    int r = ms + (lane >> 2), kp = lane & 3;
    #pragma unroll
    for (int ks = 0; ks < 4; ks++) {
        unsigned a[4];
        a[0] = sw[r * 36 + ks * 8 + kp];
        a[1] = sw[(r + 8) * 36 + ks * 8 + kp];
        a[2] = sw[r * 36 + ks * 8 + kp + 4];
        a[3] = sw[(r + 8) * 36 + ks * 8 + kp + 4];
        #pragma unroll
        for (int nt = 0; nt < NT; nt++) {
            int px = (ntb + nt) * 8 + (lane >> 2);
            unsigned b0 = sa[px * 36 + ks * 8 + kp];
            unsigned b1 = sa[px * 36 + ks * 8 + kp + 4];
            mma16816(d + nt * 4, a, b0, b1);
        }
    }
}

// ---------------- K1: LN1 stats ---------------------------------------------------
__global__ void k_stats1(const float* __restrict__ x) {
    int nc = blockIdx.x;
    const float4* p = (const float4*)(x + (size_t)nc * HW);
    float s = 0.f, q = 0.f;
    for (int j = threadIdx.x; j < HW / 4; j += 256) {
        float4 v = p[j];
        s += v.x + v.y + v.z + v.w;
        q += v.x * v.x + v.y * v.y + v.z * v.z + v.w * v.w;
    }
    __shared__ float rs[8], rq[8];
    for (int o = 16; o; o >>= 1) {
        s += __shfl_down_sync(0xffffffffu, s, o);
        q += __shfl_down_sync(0xffffffffu, q, o);
    }
    if ((threadIdx.x & 31) == 0) { rs[threadIdx.x >> 5] = s; rq[threadIdx.x >> 5] = q; }
    __syncthreads();
    if (threadIdx.x == 0) {
        float S = 0.f, Q = 0.f;
        for (int i = 0; i < 8; i++) { S += rs[i]; Q += rq[i]; }
        float m = S * (1.f / HW);
        g_mean1[nc] = m;
        g_rstd1[nc] = rsqrtf(Q * (1.f / HW) - m * m + EPSV);
    }
}

// ---------------- K2: fold LN1 -> pw1 packed bf16 ---------------------------------
__global__ void k_prep1(const float* __restrict__ ln1w, const float* __restrict__ ln1b,
                        const float* __restrict__ pw1w, const float* __restrict__ pw1b) {
    int n = blockIdx.x, o = threadIdx.x;   // 128
    float bias = pw1b[o], row[CN];
    for (int i = 0; i < CN; i++) {
        float a  = g_rstd1[n * CN + i] * ln1w[i];
        float c0 = ln1b[i] - g_mean1[n * CN + i] * a;
        float w  = pw1w[o * CN + i];
        bias += w * c0;
        row[i] = w * a;
    }
    g_b1e[n * C2 + o] = bias;
    unsigned* dst = g_w1p + (n * C2 + o) * 32;
    for (int j = 0; j < 32; j++) { unsigned pk; CVT2(pk, row[2*j], row[2*j+1]); dst[j] = pk; }
    int idx = n * C2 + o;
    if (idx < NB * CN) { g_pool[idx] = 0.f; g_sum2[idx] = 0.f; g_sumsq2[idx] = 0.f; }
}

// ---------------- K3: pw1 mma.sync GEMM -------------------------------------------
__global__ void __launch_bounds__(256) k_pw1(const float* __restrict__ x) {
    __shared__ unsigned sw[C2 * 36];
    __shared__ unsigned sa[128 * 36];
    int t = threadIdx.x, wid = t >> 5, lane = t & 31;
    int n = blockIdx.y, p0 = blockIdx.x * 128;
    copy_w(sw, g_w1p + n * C2 * 32, C2, t);
    stage_acts(sa, x, n, p0, lane, wid);
    __syncthreads();
    float d[64];
    #pragma unroll
    for (int i = 0; i < 64; i++) d[i] = 0.f;
    gemm_core<16>(sw, sa, wid * 16, 0, lane, d);
    int o1 = wid * 16 + (lane >> 2), o2 = o1 + 8;
    float bi1 = g_b1e[n * C2 + o1], bi2 = g_b1e[n * C2 + o2];
    float* u1 = g_u + (size_t)(n * C2 + o1) * HW + p0;
    float* u2 = g_u + (size_t)(n * C2 + o2) * HW + p0;
    #pragma unroll
    for (int nt = 0; nt < 16; nt++) {
        int px = nt * 8 + (lane & 3) * 2;
        *(float2*)(u1 + px) = make_float2(d[nt*4+0] + bi1, d[nt*4+1] + bi1);
        *(float2*)(u2 + px) = make_float2(d[nt*4+2] + bi2, d[nt*4+3] + bi2);
    }
}

// ---------------- K4: depthwise 3x3 + gate + pool ---------------------------------
__global__ void __launch_bounds__(256) k_dwgate(const float* __restrict__ dww,
                                                const float* __restrict__ dwb) {
    __shared__ float s[2][8][256];
    __shared__ float red[8];
    int t = threadIdx.x, tx = t & 63, ty = t >> 6;
    int nc = blockIdx.x, n = nc >> 6, c = nc & 63;
    int strip0 = blockIdx.y * 32;
    const float* u0 = g_u + ((size_t)(n * C2 + c)) * HW;
    const float* u1 = g_u + ((size_t)(n * C2 + c + 64)) * HW;
    float* gp = g_g + ((size_t)(n * CN + c)) * HW;
    float w0[9], w1[9];
    #pragma unroll
    for (int k = 0; k < 9; k++) { w0[k] = __ldg(dww + c * 9 + k); w1[k] = __ldg(dww + (c + 64) * 9 + k); }
    float b0 = __ldg(dwb + c), b1 = __ldg(dwb + c + 64);
    {
        int ch = t >> 7, ri = (t >> 6) & 1, c4 = t & 63;
        int ar = strip0 - 1 + ri;
        float4 v = make_float4(0.f, 0.f, 0.f, 0.f);
        if ((unsigned)ar < 256u) v = *(const float4*)((ch ? u1 : u0) + ar * 256 + c4 * 4);
        *(float4*)(&s[ch][(ar + 1) & 7][c4 * 4]) = v;
    }
    float psum = 0.f;
    #pragma unroll 1
    for (int g = 0; g < 8; g++) {
        #pragma unroll
        for (int k = 0; k < 2; k++) {
            int idx = t + k * 256;
            int ch = idx >> 8, ri = (idx >> 6) & 3, c4 = idx & 63;
            int ar = strip0 + 4 * g + 1 + ri;
            float4 v = make_float4(0.f, 0.f, 0.f, 0.f);
            if ((unsigned)ar < 256u) v = *(const float4*)((ch ? u1 : u0) + ar * 256 + c4 * 4);
            *(float4*)(&s[ch][(ar + 1) & 7][c4 * 4]) = v;
        }
        __syncthreads();
        int r = strip0 + 4 * g + ty;
        float a0 = b0, a1 = b0, a2 = b0, a3 = b0;
        float d0 = b1, d1 = b1, d2 = b1, d3 = b1;
        #pragma unroll
        for (int ky = 0; ky < 3; ky++) {
            int slot = (r + ky) & 7;
            const float* r0 = &s[0][slot][0];
            const float* r1 = &s[1][slot][0];
            float4 cv = *(const float4*)(r0 + tx * 4);
            float lv = tx ? r0[tx * 4 - 1] : 0.f;
            float rv = (tx != 63) ? r0[tx * 4 + 4] : 0.f;
            a0 += w0[ky*3]*lv   + w0[ky*3+1]*cv.x + w0[ky*3+2]*cv.y;
            a1 += w0[ky*3]*cv.x + w0[ky*3+1]*cv.y + w0[ky*3+2]*cv.z;
            a2 += w0[ky*3]*cv.y + w0[ky*3+1]*cv.z + w0[ky*3+2]*cv.w;
            a3 += w0[ky*3]*cv.z + w0[ky*3+1]*cv.w + w0[ky*3+2]*rv;
            float4 dv = *(const float4*)(r1 + tx * 4);
            float lw = tx ? r1[tx * 4 - 1] : 0.f;
            float rw = (tx != 63) ? r1[tx * 4 + 4] : 0.f;
            d0 += w1[ky*3]*lw   + w1[ky*3+1]*dv.x + w1[ky*3+2]*dv.y;
            d1 += w1[ky*3]*dv.x + w1[ky*3+1]*dv.y + w1[ky*3+2]*dv.z;
            d2 += w1[ky*3]*dv.y + w1[ky*3+1]*dv.z + w1[ky*3+2]*dv.w;
            d3 += w1[ky*3]*dv.z + w1[ky*3+1]*dv.w + w1[ky*3+2]*rw;
        }
        float g0 = a0 * d0, g1 = a1 * d1, g2 = a2 * d2, g3 = a3 * d3;
        *(float4*)(gp + r * 256 + tx * 4) = make_float4(g0, g1, g2, g3);
        psum += (g0 + g1) + (g2 + g3);
        __syncthreads();
    }
    for (int o = 16; o; o >>= 1) psum += __shfl_down_sync(0xffffffffu, psum, o);
    if ((t & 31) == 0) red[t >> 5] = psum;
    __syncthreads();
    if (t < 8) {
        float v = red[t];
        v += __shfl_down_sync(0xffu, v, 4);
        v += __shfl_down_sync(0xffu, v, 2);
        v += __shfl_down_sync(0xffu, v, 1);
        if (t == 0) atomicAdd(&g_pool[nc], v);
    }
}

// ---------------- K5: SCA -> pw2 packed bf16 --------------------------------------
__global__ void k_sca(const float* __restrict__ scaw, const float* __restrict__ scab,
                      const float* __restrict__ pw2w) {
    int n = blockIdx.x, o = threadIdx.x;   // 64
    __shared__ float pm[CN], sc[CN];
    pm[o] = g_pool[n * CN + o] * (1.f / HW);
    __syncthreads();
    float acc = scab[o];
    for (int i = 0; i < CN; i++) acc += scaw[o * CN + i] * pm[i];
    sc[o] = 1.f / (1.f + expf(-acc));
    __syncthreads();
    unsigned* dst = g_w2p + (n * CN + o) * 32;
    for (int j = 0; j < 32; j++) {
        unsigned pk;
        CVT2(pk, pw2w[o * CN + 2*j] * sc[2*j], pw2w[o * CN + 2*j+1] * sc[2*j+1]);
        dst[j] = pk;
    }
}

// ---------------- K6: pw2 mma GEMM + residual + LN2 stats -------------------------
__global__ void __launch_bounds__(256) k_pw2(const float* __restrict__ x,
                                             const float* __restrict__ pw2b,
                                             const float* __restrict__ beta1) {
    __shared__ unsigned sw[CN * 36];
    __shared__ unsigned sa[128 * 36];
    int t = threadIdx.x, wid = t >> 5, lane = t & 31;
    int n = blockIdx.y, p0 = blockIdx.x * 128;
    copy_w(sw, g_w2p + n * CN * 32, CN, t);
    stage_acts(sa, g_g, n, p0, lane, wid);
    __syncthreads();
    float d[32];
    #pragma unroll
    for (int i = 0; i < 32; i++) d[i] = 0.f;
    gemm_core<8>(sw, sa, (wid & 3) * 16, (wid >> 2) * 8, lane, d);
    int o1 = (wid & 3) * 16 + (lane >> 2), o2 = o1 + 8;
    float b1 = pw2b[o1], b2 = pw2b[o2], t1 = beta1[o1], t2 = beta1[o2];
    size_t off1 = (size_t)(n * CN + o1) * HW + p0;
    size_t off2 = (size_t)(n * CN + o2) * HW + p0;
    float s1 = 0.f, q1 = 0.f, s2 = 0.f, q2 = 0.f;
    #pragma unroll
    for (int nt = 0; nt < 8; nt++) {
        int px = (wid >> 2) * 64 + nt * 8 + (lane & 3) * 2;
        float2 xv1 = *(const float2*)(x + off1 + px);
        float2 xv2 = *(const float2*)(x + off2 + px);
        float2 r1 = make_float2(xv1.x + t1 * (d[nt*4+0] + b1), xv1.y + t1 * (d[nt*4+1] + b1));
        float2 r2 = make_float2(xv2.x + t2 * (d[nt*4+2] + b2), xv2.y + t2 * (d[nt*4+3] + b2));
        *(float2*)(g_x1 + off1 + px) = r1;
        *(float2*)(g_x1 + off2 + px) = r2;
        s1 += r1.x + r1.y; q1 += r1.x * r1.x + r1.y * r1.y;
        s2 += r2.x + r2.y; q2 += r2.x * r2.x + r2.y * r2.y;
    }
    s1 += __shfl_xor_sync(~0u, s1, 1); s1 += __shfl_xor_sync(~0u, s1, 2);
    q1 += __shfl_xor_sync(~0u, q1, 1); q1 += __shfl_xor_sync(~0u, q1, 2);
    s2 += __shfl_xor_sync(~0u, s2, 1); s2 += __shfl_xor_sync(~0u, s2, 2);
    q2 += __shfl_xor_sync(~0u, q2, 1); q2 += __shfl_xor_sync(~0u, q2, 2);
    if ((lane & 3) == 0) {
        atomicAdd(&g_sum2[n * CN + o1], s1);
        atomicAdd(&g_sumsq2[n * CN + o1], q1);
        atomicAdd(&g_sum2[n * CN + o2], s2);
        atomicAdd(&g_sumsq2[n * CN + o2], q2);
    }
}

// ---------------- K7: LN2 -> pw3 packed; pw4 packed -------------------------------
__global__ void k_prep3(const float* __restrict__ ln2w, const float* __restrict__ ln2b,
                        const float* __restrict__ pw3w, const float* __restrict__ pw3b,
                        const float* __restrict__ pw4w) {
    int n = blockIdx.x, o = threadIdx.x;   // 128
    __shared__ float m2[CN], r2[CN];
    if (o < CN) {
        float m = g_sum2[n * CN + o] * (1.f / HW);
        m2[o] = m;
        r2[o] = rsqrtf(g_sumsq2[n * CN + o] * (1.f / HW) - m * m + EPSV);
    }
    __syncthreads();
    float bias = pw3b[o], row[CN];
    for (int i = 0; i < CN; i++) {
        float a  = r2[i] * ln2w[i];
        float c0 = ln2b[i] - m2[i] * a;
        float w  = pw3w[o * CN + i];
        bias += w * c0;
        row[i] = w * a;
    }
    g_b3e[n * C2 + o] = bias;
    unsigned* dst = g_w3p + (n * C2 + o) * 32;
    for (int j = 0; j < 32; j++) { unsigned pk; CVT2(pk, row[2*j], row[2*j+1]); dst[j] = pk; }
    if (n == 0 && o < CN) {
        unsigned* d4 = g_w4p + o * 32;
        for (int j = 0; j < 32; j++) {
            unsigned pk; CVT2(pk, pw4w[o * CN + 2*j], pw4w[o * CN + 2*j+1]);
            d4[j] = pk;
        }
    }
}

// ---------------- K8: pw3 MMA -> gate -> pw4 MMA -> residual -> out ---------------
__global__ void __launch_bounds__(256) k_final(const float* __restrict__ pw4b,
                                               const float* __restrict__ beta2,
                                               float* __restrict__ out) {
    extern __shared__ __align__(16) char smem[];
    float*    x1s  = (float*)smem;                              // [128][66] fp32 = 33792
    unsigned* w3   = (unsigned*)(smem + 33792);                 // 18432
    unsigned* w4   = (unsigned*)(smem + 33792 + 18432);         // 9216
    unsigned* bufB = (unsigned*)(smem + 33792 + 18432 + 9216);  // 18432 (B3 then B4)
    unsigned short* sc2 = (unsigned short*)w3;                  // overlay after pw3
    int t = threadIdx.x, wid = t >> 5, lane = t & 31;
    int n = blockIdx.y, p0 = blockIdx.x * 128;
    copy_w(w3, g_w3p + n * C2 * 32, C2, t);
    copy_w(w4, g_w4p, CN, t);
    {   // stage x1: fp32 tile + bf16 B3
        const float4* xa = (const float4*)(g_x1 + ((size_t)(n * CN + 2 * lane)) * HW) + (p0 >> 2);
        const float4* xb = xa + (HW >> 2);
        float2* x1s2 = (float2*)x1s;
        #pragma unroll
        for (int j = 0; j < 4; j++) {
            int px4 = wid * 4 + j;
            float4 a = xa[px4], b = xb[px4];
            int p = px4 * 4;
            x1s2[(p + 0) * 33 + lane] = make_float2(a.x, b.x);
            x1s2[(p + 1) * 33 + lane] = make_float2(a.y, b.y);
            x1s2[(p + 2) * 33 + lane] = make_float2(a.z, b.z);
            x1s2[(p + 3) * 33 + lane] = make_float2(a.w, b.w);
            unsigned v0, v1, v2, v3;
            CVT2(v0, a.x, b.x); CVT2(v1, a.y, b.y); CVT2(v2, a.z, b.z); CVT2(v3, a.w, b.w);
            bufB[(p + 0) * 36 + lane] = v0;
            bufB[(p + 1) * 36 + lane] = v1;
            bufB[(p + 2) * 36 + lane] = v2;
            bufB[(p + 3) * 36 + lane] = v3;
        }
    }
    __syncthreads();
    float d[64];
    #pragma unroll
    for (int i = 0; i < 64; i++) d[i] = 0.f;
    gemm_core<16>(w3, bufB, wid * 16, 0, lane, d);
    int r1 = wid * 16 + (lane >> 2), r2 = r1 + 8;
    float b31 = g_b3e[n * C2 + r1], b32 = g_b3e[n * C2 + r2];
    __syncthreads();   // all warps done reading w3/bufB
    if (wid >= 4) {    // hi half: write y_hi bf16 into sc2 [px][72]
        int c1 = r1 - 64, c2 = r2 - 64;
        #pragma unroll
        for (int nt = 0; nt < 16; nt++) {
            int px = nt * 8 + (lane & 3) * 2;
            sc2[px * 72 + c1]       = __bfloat16_as_ushort(__float2bfloat16_rn(d[nt*4+0] + b31));
            sc2[(px + 1) * 72 + c1] = __bfloat16_as_ushort(__float2bfloat16_rn(d[nt*4+1] + b31));
            sc2[px * 72 + c2]       = __bfloat16_as_ushort(__float2bfloat16_rn(d[nt*4+2] + b32));
            sc2[(px + 1) * 72 + c2] = __bfloat16_as_ushort(__float2bfloat16_rn(d[nt*4+3] + b32));
        }
    }
    __syncthreads();
    if (wid < 4) {     // lo half: gate and write B4 bf16 into bufB [px][72]
        unsigned short* b4s = (unsigned short*)bufB;
        #pragma unroll
        for (int nt = 0; nt < 16; nt++) {
            int px = nt * 8 + (lane & 3) * 2;
            float h0 = __bfloat162float(__ushort_as_bfloat16(sc2[px * 72 + r1]));
            float h1 = __bfloat162float(__ushort_as_bfloat16(sc2[(px + 1) * 72 + r1]));
            float h2 = __bfloat162float(__ushort_as_bfloat16(sc2[px * 72 + r2]));
            float h3 = __bfloat162float(__ushort_as_bfloat16(sc2[(px + 1) * 72 + r2]));
            b4s[px * 72 + r1]       = __bfloat16_as_ushort(__float2bfloat16_rn((d[nt*4+0] + b31) * h0));
            b4s[(px + 1) * 72 + r1] = __bfloat16_as_ushort(__float2bfloat16_rn((d[nt*4+1] + b31) * h1));
            b4s[px * 72 + r2]       = __bfloat16_as_ushort(__float2bfloat16_rn((d[nt*4+2] + b32) * h2));
            b4s[(px + 1) * 72 + r2] = __bfloat16_as_ushort(__float2bfloat16_rn((d[nt*4+3] + b32) * h3));
        }
    }
    __syncthreads();
    float e[32];
    #pragma unroll
    for (int i = 0; i < 32; i++) e[i] = 0.f;
    gemm_core<8>(w4, bufB, (wid & 3) * 16, (wid >> 2) * 8, lane, e);
    int o1 = (wid & 3) * 16 + (lane >> 2), o2 = o1 + 8;
    float b41 = pw4b[o1], b42 = pw4b[o2], t41 = beta2[o1], t42 = beta2[o2];
    float* op1 = out + (size_t)(n * CN + o1) * HW + p0;
    float* op2 = out + (size_t)(n * CN + o2) * HW + p0;
    #pragma unroll
    for (int nt = 0; nt < 8; nt++) {
        int px = (wid >> 2) * 64 + nt * 8 + (lane & 3) * 2;
        float2 r1v, r2v;
        r1v.x = x1s[px * 66 + o1]       + t41 * (e[nt*4+0] + b41);
        r1v.y = x1s[(px + 1) * 66 + o1] + t41 * (e[nt*4+1] + b41);
        r2v.x = x1s[px * 66 + o2]       + t42 * (e[nt*4+2] + b42);
        r2v.y = x1s[(px + 1) * 66 + o2] + t42 * (e[nt*4+3] + b42);
        *(float2*)(op1 + px) = r1v;
        *(float2*)(op2 + px) = r2v;
    }
}

// ---------------- host ------------------------------------------------------------
extern "C" void kernel_launch(void* const* d_in, const int* in_sizes, int n_in,
                              void* d_out, int out_size) {
    const float* x     = (const float*)d_in[0];
    const float* ln1w  = (const float*)d_in[1];
    const float* ln1b  = (const float*)d_in[2];
    const float* pw1w  = (const float*)d_in[3];
    const float* pw1b  = (const float*)d_in[4];
    const float* dww   = (const float*)d_in[5];
    const float* dwb   = (const float*)d_in[6];
    const float* scaw  = (const float*)d_in[7];
    const float* scab  = (const float*)d_in[8];
    const float* pw2w  = (const float*)d_in[9];
    const float* pw2b  = (const float*)d_in[10];
    const float* ln2w  = (const float*)d_in[11];
    const float* ln2b  = (const float*)d_in[12];
    const float* pw3w  = (const float*)d_in[13];
    const float* pw3b  = (const float*)d_in[14];
    const float* pw4w  = (const float*)d_in[15];
    const float* pw4b  = (const float*)d_in[16];
    const float* beta1 = (const float*)d_in[17];
    const float* beta2 = (const float*)d_in[18];

    cudaFuncSetAttribute(k_final, cudaFuncAttributeMaxDynamicSharedMemorySize, 80 * 1024);

    k_stats1<<<NB * CN, 256>>>(x);
    k_prep1<<<NB, C2>>>(ln1w, ln1b, pw1w, pw1b);
    k_pw1<<<dim3(512, NB), 256>>>(x);
    k_dwgate<<<dim3(NB * CN, 8), 256>>>(dww, dwb);
    k_sca<<<NB, CN>>>(scaw, scab, pw2w);
    k_pw2<<<dim3(512, NB), 256>>>(x, pw2b, beta1);
    k_prep3<<<NB, C2>>>(ln2w, ln2b, pw3w, pw3b, pw4w);
    k_final<<<dim3(512, NB), 256, 80 * 1024>>>(pw4b, beta2, (float*)d_out);
}

// round 8
// speedup vs baseline: 2.0827x; 1.0303x over previous
#include <cuda_runtime.h>
#include <cuda_bf16.h>
#include <cstdint>

#define HW 65536
#define CN 64
#define C2 128
#define NB 8
#define EPSV 1e-6f

__device__ unsigned short g_u[(size_t)NB*C2*HW];   // bf16 pw1 output, 134MB
__device__ unsigned short g_g[(size_t)NB*CN*HW];   // bf16 gated, 67MB
__device__ float g_x1[(size_t)NB*CN*HW];           // fp32 first residual, 134MB
__device__ float g_mean1[NB*CN], g_rstd1[NB*CN], g_pool[NB*CN], g_sum2[NB*CN], g_sumsq2[NB*CN];
__device__ float g_b1e[NB*C2], g_b3e[NB*C2];
__device__ __align__(16) unsigned g_w1p[NB*C2*32];
__device__ __align__(16) unsigned g_w2p[NB*CN*32];
__device__ __align__(16) unsigned g_w3p[NB*C2*32];
__device__ __align__(16) unsigned g_w4p[CN*32];

// res = {lo: a, hi: b}
#define CVT2(res,a,b) asm("cvt.rn.satfinite.bf16x2.f32 %0, %1, %2;" : "=r"(res) : "f"(b), "f"(a))
#define BF2F(u) __bfloat162float(__ushort_as_bfloat16(u))

__device__ __forceinline__ void mma16816(float* d, const unsigned* a, unsigned b0, unsigned b1) {
    asm volatile("mma.sync.aligned.m16n8k16.row.col.f32.bf16.bf16.f32 "
        "{%0,%1,%2,%3}, {%4,%5,%6,%7}, {%8,%9}, {%0,%1,%2,%3};"
        : "+f"(d[0]), "+f"(d[1]), "+f"(d[2]), "+f"(d[3])
        : "r"(a[0]), "r"(a[1]), "r"(a[2]), "r"(a[3]), "r"(b0), "r"(b1));
}

// stage fp32 ch-major activations -> bf16 [128px][36 words], 256 threads
__device__ __forceinline__ void stage_acts_f32(unsigned* sa, const float* src, int n, int p0,
                                               int lane, int wid) {
    const float4* xa = (const float4*)(src + ((size_t)(n * CN + 2 * lane)) * HW) + (p0 >> 2);
    const float4* xb = xa + (HW >> 2);
    #pragma unroll
    for (int j = 0; j < 4; j++) {
        int px4 = wid * 4 + j;
        float4 a = xa[px4], b = xb[px4];
        int p = px4 * 4;
        unsigned v0, v1, v2, v3;
        CVT2(v0, a.x, b.x); CVT2(v1, a.y, b.y); CVT2(v2, a.z, b.z); CVT2(v3, a.w, b.w);
        sa[(p + 0) * 36 + lane] = v0;
        sa[(p + 1) * 36 + lane] = v1;
        sa[(p + 2) * 36 + lane] = v2;
        sa[(p + 3) * 36 + lane] = v3;
    }
}

// stage bf16 ch-major activations -> [128px][36 words] (pure repack, no rounding)
__device__ __forceinline__ void stage_acts_bf16(unsigned* sa, const unsigned short* src,
                                                int n, int p0, int lane, int wid) {
    const ushort4* ga = (const ushort4*)(src + ((size_t)(n * CN + 2 * lane)) * HW + p0);
    const ushort4* gb = ga + (HW >> 2);
    #pragma unroll
    for (int j = 0; j < 4; j++) {
        int px4 = wid * 4 + j;
        ushort4 a = ga[px4], b = gb[px4];
        int p = px4 * 4;
        sa[(p + 0) * 36 + lane] = (unsigned)a.x | ((unsigned)b.x << 16);
        sa[(p + 1) * 36 + lane] = (unsigned)a.y | ((unsigned)b.y << 16);
        sa[(p + 2) * 36 + lane] = (unsigned)a.z | ((unsigned)b.z << 16);
        sa[(p + 3) * 36 + lane] = (unsigned)a.w | ((unsigned)b.w << 16);
    }
}

__device__ __forceinline__ void copy_w(unsigned* sw, const unsigned* gw, int rows, int t) {
    int r = t >> 5, w = t & 31;
    for (; r < rows; r += 8) sw[r * 36 + w] = gw[r * 32 + w];
}

template<int NT>
__device__ __forceinline__ void gemm_core(const unsigned* sw, const unsigned* sa,
                                          int ms, int ntb, int lane, float* d) {
    int r = ms + (lane >> 2), kp = lane & 3;
    #pragma unroll
    for (int ks = 0; ks < 4; ks++) {
        unsigned a[4];
        a[0] = sw[r * 36 + ks * 8 + kp];
        a[1] = sw[(r + 8) * 36 + ks * 8 + kp];
        a[2] = sw[r * 36 + ks * 8 + kp + 4];
        a[3] = sw[(r + 8) * 36 + ks * 8 + kp + 4];
        #pragma unroll
        for (int nt = 0; nt < NT; nt++) {
            int px = (ntb + nt) * 8 + (lane >> 2);
            unsigned b0 = sa[px * 36 + ks * 8 + kp];
            unsigned b1 = sa[px * 36 + ks * 8 + kp + 4];
            mma16816(d + nt * 4, a, b0, b1);
        }
    }
}

// ---------------- K1: LN1 stats ---------------------------------------------------
__global__ void k_stats1(const float* __restrict__ x) {
    int nc = blockIdx.x;
    const float4* p = (const float4*)(x + (size_t)nc * HW);
    float s = 0.f, q = 0.f;
    for (int j = threadIdx.x; j < HW / 4; j += 256) {
        float4 v = p[j];
        s += v.x + v.y + v.z + v.w;
        q += v.x * v.x + v.y * v.y + v.z * v.z + v.w * v.w;
    }
    __shared__ float rs[8], rq[8];
    for (int o = 16; o; o >>= 1) {
        s += __shfl_down_sync(0xffffffffu, s, o);
        q += __shfl_down_sync(0xffffffffu, q, o);
    }
    if ((threadIdx.x & 31) == 0) { rs[threadIdx.x >> 5] = s; rq[threadIdx.x >> 5] = q; }
    __syncthreads();
    if (threadIdx.x == 0) {
        float S = 0.f, Q = 0.f;
        for (int i = 0; i < 8; i++) { S += rs[i]; Q += rq[i]; }
        float m = S * (1.f / HW);
        g_mean1[nc] = m;
        g_rstd1[nc] = rsqrtf(Q * (1.f / HW) - m * m + EPSV);
    }
}

// ---------------- K2: fold LN1 -> pw1 packed bf16 ---------------------------------
__global__ void k_prep1(const float* __restrict__ ln1w, const float* __restrict__ ln1b,
                        const float* __restrict__ pw1w, const float* __restrict__ pw1b) {
    int n = blockIdx.x, o = threadIdx.x;   // 128
    float bias = pw1b[o], row[CN];
    for (int i = 0; i < CN; i++) {
        float a  = g_rstd1[n * CN + i] * ln1w[i];
        float c0 = ln1b[i] - g_mean1[n * CN + i] * a;
        float w  = pw1w[o * CN + i];
        bias += w * c0;
        row[i] = w * a;
    }
    g_b1e[n * C2 + o] = bias;
    unsigned* dst = g_w1p + (n * C2 + o) * 32;
    for (int j = 0; j < 32; j++) { unsigned pk; CVT2(pk, row[2*j], row[2*j+1]); dst[j] = pk; }
    int idx = n * C2 + o;
    if (idx < NB * CN) { g_pool[idx] = 0.f; g_sum2[idx] = 0.f; g_sumsq2[idx] = 0.f; }
}

// ---------------- K3: pw1 mma.sync GEMM (bf16 out) --------------------------------
__global__ void __launch_bounds__(256) k_pw1(const float* __restrict__ x) {
    __shared__ unsigned sw[C2 * 36];
    __shared__ unsigned sa[128 * 36];
    int t = threadIdx.x, wid = t >> 5, lane = t & 31;
    int n = blockIdx.y, p0 = blockIdx.x * 128;
    copy_w(sw, g_w1p + n * C2 * 32, C2, t);
    stage_acts_f32(sa, x, n, p0, lane, wid);
    __syncthreads();
    float d[64];
    #pragma unroll
    for (int i = 0; i < 64; i++) d[i] = 0.f;
    gemm_core<16>(sw, sa, wid * 16, 0, lane, d);
    int o1 = wid * 16 + (lane >> 2), o2 = o1 + 8;
    float bi1 = g_b1e[n * C2 + o1], bi2 = g_b1e[n * C2 + o2];
    unsigned short* u1 = g_u + (size_t)(n * C2 + o1) * HW + p0;
    unsigned short* u2 = g_u + (size_t)(n * C2 + o2) * HW + p0;
    #pragma unroll
    for (int nt = 0; nt < 16; nt++) {
        int px = nt * 8 + (lane & 3) * 2;
        unsigned pk1, pk2;
        CVT2(pk1, d[nt*4+0] + bi1, d[nt*4+1] + bi1);
        CVT2(pk2, d[nt*4+2] + bi2, d[nt*4+3] + bi2);
        *(unsigned*)(u1 + px) = pk1;
        *(unsigned*)(u2 + px) = pk2;
    }
}

// ---------------- K4: depthwise 3x3 + gate + pool (bf16 in/out) -------------------
__global__ void __launch_bounds__(256) k_dwgate(const float* __restrict__ dww,
                                                const float* __restrict__ dwb) {
    __shared__ float s[2][8][256];
    __shared__ float red[8];
    int t = threadIdx.x, tx = t & 63, ty = t >> 6;
    int nc = blockIdx.x, n = nc >> 6, c = nc & 63;
    int strip0 = blockIdx.y * 32;
    const unsigned short* u0 = g_u + ((size_t)(n * C2 + c)) * HW;
    const unsigned short* u1 = g_u + ((size_t)(n * C2 + c + 64)) * HW;
    unsigned short* gp = g_g + ((size_t)(n * CN + c)) * HW;
    float w0[9], w1[9];
    #pragma unroll
    for (int k = 0; k < 9; k++) { w0[k] = __ldg(dww + c * 9 + k); w1[k] = __ldg(dww + (c + 64) * 9 + k); }
    float b0 = __ldg(dwb + c), b1 = __ldg(dwb + c + 64);
    {   // prologue rows strip0-1, strip0: 2ch x 2rows x 64 chunks = 256
        int ch = t >> 7, ri = (t >> 6) & 1, c8 = t & 63;
        int ar = strip0 - 1 + ri;
        float4 f = make_float4(0.f, 0.f, 0.f, 0.f);
        if ((unsigned)ar < 256u) {
            ushort4 v = *(const ushort4*)((ch ? u1 : u0) + ar * 256 + c8 * 4);
            f = make_float4(BF2F(v.x), BF2F(v.y), BF2F(v.z), BF2F(v.w));
        }
        *(float4*)(&s[ch][(ar + 1) & 7][c8 * 4]) = f;
    }
    float psum = 0.f;
    #pragma unroll 1
    for (int g = 0; g < 8; g++) {
        #pragma unroll
        for (int k = 0; k < 2; k++) {   // 2ch x 4rows x 64 chunks = 512
            int idx = t + k * 256;
            int ch = idx >> 8, ri = (idx >> 6) & 3, c8 = idx & 63;
            int ar = strip0 + 4 * g + 1 + ri;
            float4 f = make_float4(0.f, 0.f, 0.f, 0.f);
            if ((unsigned)ar < 256u) {
                ushort4 v = *(const ushort4*)((ch ? u1 : u0) + ar * 256 + c8 * 4);
                f = make_float4(BF2F(v.x), BF2F(v.y), BF2F(v.z), BF2F(v.w));
            }
            *(float4*)(&s[ch][(ar + 1) & 7][c8 * 4]) = f;
        }
        __syncthreads();
        int r = strip0 + 4 * g + ty;
        float a0 = b0, a1 = b0, a2 = b0, a3 = b0;
        float d0 = b1, d1 = b1, d2 = b1, d3 = b1;
        #pragma unroll
        for (int ky = 0; ky < 3; ky++) {
            int slot = (r + ky) & 7;
            const float* r0 = &s[0][slot][0];
            const float* r1 = &s[1][slot][0];
            float4 cv = *(const float4*)(r0 + tx * 4);
            float lv = tx ? r0[tx * 4 - 1] : 0.f;
            float rv = (tx != 63) ? r0[tx * 4 + 4] : 0.f;
            a0 += w0[ky*3]*lv   + w0[ky*3+1]*cv.x + w0[ky*3+2]*cv.y;
            a1 += w0[ky*3]*cv.x + w0[ky*3+1]*cv.y + w0[ky*3+2]*cv.z;
            a2 += w0[ky*3]*cv.y + w0[ky*3+1]*cv.z + w0[ky*3+2]*cv.w;
            a3 += w0[ky*3]*cv.z + w0[ky*3+1]*cv.w + w0[ky*3+2]*rv;
            float4 dv = *(const float4*)(r1 + tx * 4);
            float lw = tx ? r1[tx * 4 - 1] : 0.f;
            float rw = (tx != 63) ? r1[tx * 4 + 4] : 0.f;
            d0 += w1[ky*3]*lw   + w1[ky*3+1]*dv.x + w1[ky*3+2]*dv.y;
            d1 += w1[ky*3]*dv.x + w1[ky*3+1]*dv.y + w1[ky*3+2]*dv.z;
            d2 += w1[ky*3]*dv.y + w1[ky*3+1]*dv.z + w1[ky*3+2]*dv.w;
            d3 += w1[ky*3]*dv.z + w1[ky*3+1]*dv.w + w1[ky*3+2]*rw;
        }
        float g0 = a0 * d0, g1 = a1 * d1, g2 = a2 * d2, g3 = a3 * d3;
        unsigned pk0, pk1;
        CVT2(pk0, g0, g1); CVT2(pk1, g2, g3);
        *(uint2*)(gp + r * 256 + tx * 4) = make_uint2(pk0, pk1);
        psum += (g0 + g1) + (g2 + g3);
        __syncthreads();
    }
    for (int o = 16; o; o >>= 1) psum += __shfl_down_sync(0xffffffffu, psum, o);
    if ((t & 31) == 0) red[t >> 5] = psum;
    __syncthreads();
    if (t < 8) {
        float v = red[t];
        v += __shfl_down_sync(0xffu, v, 4);
        v += __shfl_down_sync(0xffu, v, 2);
        v += __shfl_down_sync(0xffu, v, 1);
        if (t == 0) atomicAdd(&g_pool[nc], v);
    }
}

// ---------------- K5: SCA -> pw2 packed bf16 --------------------------------------
__global__ void k_sca(const float* __restrict__ scaw, const float* __restrict__ scab,
                      const float* __restrict__ pw2w) {
    int n = blockIdx.x, o = threadIdx.x;   // 64
    __shared__ float pm[CN], sc[CN];
    pm[o] = g_pool[n * CN + o] * (1.f / HW);
    __syncthreads();
    float acc = scab[o];
    for (int i = 0; i < CN; i++) acc += scaw[o * CN + i] * pm[i];
    sc[o] = 1.f / (1.f + expf(-acc));
    __syncthreads();
    unsigned* dst = g_w2p + (n * CN + o) * 32;
    for (int j = 0; j < 32; j++) {
        unsigned pk;
        CVT2(pk, pw2w[o * CN + 2*j] * sc[2*j], pw2w[o * CN + 2*j+1] * sc[2*j+1]);
        dst[j] = pk;
    }
}

// ---------------- K6: pw2 mma GEMM + residual + LN2 stats -------------------------
__global__ void __launch_bounds__(256) k_pw2(const float* __restrict__ x,
                                             const float* __restrict__ pw2b,
                                             const float* __restrict__ beta1) {
    __shared__ unsigned sw[CN * 36];
    __shared__ unsigned sa[128 * 36];
    int t = threadIdx.x, wid = t >> 5, lane = t & 31;
    int n = blockIdx.y, p0 = blockIdx.x * 128;
    copy_w(sw, g_w2p + n * CN * 32, CN, t);
    stage_acts_bf16(sa, g_g, n, p0, lane, wid);
    __syncthreads();
    float d[32];
    #pragma unroll
    for (int i = 0; i < 32; i++) d[i] = 0.f;
    gemm_core<8>(sw, sa, (wid & 3) * 16, (wid >> 2) * 8, lane, d);
    int o1 = (wid & 3) * 16 + (lane >> 2), o2 = o1 + 8;
    float b1 = pw2b[o1], b2 = pw2b[o2], t1 = beta1[o1], t2 = beta1[o2];
    size_t off1 = (size_t)(n * CN + o1) * HW + p0;
    size_t off2 = (size_t)(n * CN + o2) * HW + p0;
    float s1 = 0.f, q1 = 0.f, s2 = 0.f, q2 = 0.f;
    #pragma unroll
    for (int nt = 0; nt < 8; nt++) {
        int px = (wid >> 2) * 64 + nt * 8 + (lane & 3) * 2;
        float2 xv1 = *(const float2*)(x + off1 + px);
        float2 xv2 = *(const float2*)(x + off2 + px);
        float2 r1 = make_float2(xv1.x + t1 * (d[nt*4+0] + b1), xv1.y + t1 * (d[nt*4+1] + b1));
        float2 r2 = make_float2(xv2.x + t2 * (d[nt*4+2] + b2), xv2.y + t2 * (d[nt*4+3] + b2));
        *(float2*)(g_x1 + off1 + px) = r1;
        *(float2*)(g_x1 + off2 + px) = r2;
        s1 += r1.x + r1.y; q1 += r1.x * r1.x + r1.y * r1.y;
        s2 += r2.x + r2.y; q2 += r2.x * r2.x + r2.y * r2.y;
    }
    s1 += __shfl_xor_sync(~0u, s1, 1); s1 += __shfl_xor_sync(~0u, s1, 2);
    q1 += __shfl_xor_sync(~0u, q1, 1); q1 += __shfl_xor_sync(~0u, q1, 2);
    s2 += __shfl_xor_sync(~0u, s2, 1); s2 += __shfl_xor_sync(~0u, s2, 2);
    q2 += __shfl_xor_sync(~0u, q2, 1); q2 += __shfl_xor_sync(~0u, q2, 2);
    if ((lane & 3) == 0) {
        atomicAdd(&g_sum2[n * CN + o1], s1);
        atomicAdd(&g_sumsq2[n * CN + o1], q1);
        atomicAdd(&g_sum2[n * CN + o2], s2);
        atomicAdd(&g_sumsq2[n * CN + o2], q2);
    }
}

// ---------------- K7: LN2 -> pw3 packed; pw4 packed -------------------------------
__global__ void k_prep3(const float* __restrict__ ln2w, const float* __restrict__ ln2b,
                        const float* __restrict__ pw3w, const float* __restrict__ pw3b,
                        const float* __restrict__ pw4w) {
    int n = blockIdx.x, o = threadIdx.x;   // 128
    __shared__ float m2[CN], r2[CN];
    if (o < CN) {
        float m = g_sum2[n * CN + o] * (1.f / HW);
        m2[o] = m;
        r2[o] = rsqrtf(g_sumsq2[n * CN + o] * (1.f / HW) - m * m + EPSV);
    }
    __syncthreads();
    float bias = pw3b[o], row[CN];
    for (int i = 0; i < CN; i++) {
        float a  = r2[i] * ln2w[i];
        float c0 = ln2b[i] - m2[i] * a;
        float w  = pw3w[o * CN + i];
        bias += w * c0;
        row[i] = w * a;
    }
    g_b3e[n * C2 + o] = bias;
    unsigned* dst = g_w3p + (n * C2 + o) * 32;
    for (int j = 0; j < 32; j++) { unsigned pk; CVT2(pk, row[2*j], row[2*j+1]); dst[j] = pk; }
    if (n == 0 && o < CN) {
        unsigned* d4 = g_w4p + o * 32;
        for (int j = 0; j < 32; j++) {
            unsigned pk; CVT2(pk, pw4w[o * CN + 2*j], pw4w[o * CN + 2*j+1]);
            d4[j] = pk;
        }
    }
}

// ---------------- K8: pw3 MMA -> gate -> pw4 MMA -> residual -> out ---------------
__global__ void __launch_bounds__(256) k_final(const float* __restrict__ pw4b,
                                               const float* __restrict__ beta2,
                                               float* __restrict__ out) {
    extern __shared__ __align__(16) char smem[];
    float*    x1s  = (float*)smem;                              // [128][66] fp32 = 33792
    unsigned* w3   = (unsigned*)(smem + 33792);                 // 18432
    unsigned* w4   = (unsigned*)(smem + 33792 + 18432);         // 9216
    unsigned* bufB = (unsigned*)(smem + 33792 + 18432 + 9216);  // 18432 (B3 then B4)
    unsigned short* sc2 = (unsigned short*)w3;                  // overlay after pw3
    int t = threadIdx.x, wid = t >> 5, lane = t & 31;
    int n = blockIdx.y, p0 = blockIdx.x * 128;
    copy_w(w3, g_w3p + n * C2 * 32, C2, t);
    copy_w(w4, g_w4p, CN, t);
    {
        const float4* xa = (const float4*)(g_x1 + ((size_t)(n * CN + 2 * lane)) * HW) + (p0 >> 2);
        const float4* xb = xa + (HW >> 2);
        float2* x1s2 = (float2*)x1s;
        #pragma unroll
        for (int j = 0; j < 4; j++) {
            int px4 = wid * 4 + j;
            float4 a = xa[px4], b = xb[px4];
            int p = px4 * 4;
            x1s2[(p + 0) * 33 + lane] = make_float2(a.x, b.x);
            x1s2[(p + 1) * 33 + lane] = make_float2(a.y, b.y);
            x1s2[(p + 2) * 33 + lane] = make_float2(a.z, b.z);
            x1s2[(p + 3) * 33 + lane] = make_float2(a.w, b.w);
            unsigned v0, v1, v2, v3;
            CVT2(v0, a.x, b.x); CVT2(v1, a.y, b.y); CVT2(v2, a.z, b.z); CVT2(v3, a.w, b.w);
            bufB[(p + 0) * 36 + lane] = v0;
            bufB[(p + 1) * 36 + lane] = v1;
            bufB[(p + 2) * 36 + lane] = v2;
            bufB[(p + 3) * 36 + lane] = v3;
        }
    }
    __syncthreads();
    float d[64];
    #pragma unroll
    for (int i = 0; i < 64; i++) d[i] = 0.f;
    gemm_core<16>(w3, bufB, wid * 16, 0, lane, d);
    int r1 = wid * 16 + (lane >> 2), r2 = r1 + 8;
    float b31 = g_b3e[n * C2 + r1], b32 = g_b3e[n * C2 + r2];
    __syncthreads();
    if (wid >= 4) {
        int c1 = r1 - 64, c2 = r2 - 64;
        #pragma unroll
        for (int nt = 0; nt < 16; nt++) {
            int px = nt * 8 + (lane & 3) * 2;
            sc2[px * 72 + c1]       = __bfloat16_as_ushort(__float2bfloat16_rn(d[nt*4+0] + b31));
            sc2[(px + 1) * 72 + c1] = __bfloat16_as_ushort(__float2bfloat16_rn(d[nt*4+1] + b31));
            sc2[px * 72 + c2]       = __bfloat16_as_ushort(__float2bfloat16_rn(d[nt*4+2] + b32));
            sc2[(px + 1) * 72 + c2] = __bfloat16_as_ushort(__float2bfloat16_rn(d[nt*4+3] + b32));
        }
    }
    __syncthreads();
    if (wid < 4) {
        unsigned short* b4s = (unsigned short*)bufB;
        #pragma unroll
        for (int nt = 0; nt < 16; nt++) {
            int px = nt * 8 + (lane & 3) * 2;
            float h0 = BF2F(sc2[px * 72 + r1]);
            float h1 = BF2F(sc2[(px + 1) * 72 + r1]);
            float h2 = BF2F(sc2[px * 72 + r2]);
            float h3 = BF2F(sc2[(px + 1) * 72 + r2]);
            b4s[px * 72 + r1]       = __bfloat16_as_ushort(__float2bfloat16_rn((d[nt*4+0] + b31) * h0));
            b4s[(px + 1) * 72 + r1] = __bfloat16_as_ushort(__float2bfloat16_rn((d[nt*4+1] + b31) * h1));
            b4s[px * 72 + r2]       = __bfloat16_as_ushort(__float2bfloat16_rn((d[nt*4+2] + b32) * h2));
            b4s[(px + 1) * 72 + r2] = __bfloat16_as_ushort(__float2bfloat16_rn((d[nt*4+3] + b32) * h3));
        }
    }
    __syncthreads();
    float e[32];
    #pragma unroll
    for (int i = 0; i < 32; i++) e[i] = 0.f;
    gemm_core<8>(w4, bufB, (wid & 3) * 16, (wid >> 2) * 8, lane, e);
    int o1 = (wid & 3) * 16 + (lane >> 2), o2 = o1 + 8;
    float b41 = pw4b[o1], b42 = pw4b[o2], t41 = beta2[o1], t42 = beta2[o2];
    float* op1 = out + (size_t)(n * CN + o1) * HW + p0;
    float* op2 = out + (size_t)(n * CN + o2) * HW + p0;
    #pragma unroll
    for (int nt = 0; nt < 8; nt++) {
        int px = (wid >> 2) * 64 + nt * 8 + (lane & 3) * 2;
        float2 r1v, r2v;
        r1v.x = x1s[px * 66 + o1]       + t41 * (e[nt*4+0] + b41);
        r1v.y = x1s[(px + 1) * 66 + o1] + t41 * (e[nt*4+1] + b41);
        r2v.x = x1s[px * 66 + o2]       + t42 * (e[nt*4+2] + b42);
        r2v.y = x1s[(px + 1) * 66 + o2] + t42 * (e[nt*4+3] + b42);
        *(float2*)(op1 + px) = r1v;
        *(float2*)(op2 + px) = r2v;
    }
}

// ---------------- host ------------------------------------------------------------
extern "C" void kernel_launch(void* const* d_in, const int* in_sizes, int n_in,
                              void* d_out, int out_size) {
    const float* x     = (const float*)d_in[0];
    const float* ln1w  = (const float*)d_in[1];
    const float* ln1b  = (const float*)d_in[2];
    const float* pw1w  = (const float*)d_in[3];
    const float* pw1b  = (const float*)d_in[4];
    const float* dww   = (const float*)d_in[5];
    const float* dwb   = (const float*)d_in[6];
    const float* scaw  = (const float*)d_in[7];
    const float* scab  = (const float*)d_in[8];
    const float* pw2w  = (const float*)d_in[9];
    const float* pw2b  = (const float*)d_in[10];
    const float* ln2w  = (const float*)d_in[11];
    const float* ln2b  = (const float*)d_in[12];
    const float* pw3w  = (const float*)d_in[13];
    const float* pw3b  = (const float*)d_in[14];
    const float* pw4w  = (const float*)d_in[15];
    const float* pw4b  = (const float*)d_in[16];
    const float* beta1 = (const float*)d_in[17];
    const float* beta2 = (const float*)d_in[18];

    cudaFuncSetAttribute(k_final, cudaFuncAttributeMaxDynamicSharedMemorySize, 80 * 1024);

    k_stats1<<<NB * CN, 256>>>(x);
    k_prep1<<<NB, C2>>>(ln1w, ln1b, pw1w, pw1b);
    k_pw1<<<dim3(512, NB), 256>>>(x);
    k_dwgate<<<dim3(NB * CN, 8), 256>>>(dww, dwb);
    k_sca<<<NB, CN>>>(scaw, scab, pw2w);
    k_pw2<<<dim3(512, NB), 256>>>(x, pw2b, beta1);
    k_prep3<<<NB, C2>>>(ln2w, ln2b, pw3w, pw3b, pw4w);
    k_final<<<dim3(512, NB), 256, 80 * 1024>>>(pw4b, beta2, (float*)d_out);
}

// round 11
// speedup vs baseline: 2.2378x; 1.0745x over previous
#include <cuda_runtime.h>
#include <cuda_bf16.h>
#include <cstdint>

#define HW 65536
#define CN 64
#define C2 128
#define NB 8
#define EPSV 1e-6f

__device__ unsigned short g_u[(size_t)NB*C2*HW];   // bf16 pw1 output, 134MB
__device__ unsigned short g_g[(size_t)NB*CN*HW];   // bf16 gated, 67MB
__device__ float g_x1[(size_t)NB*CN*HW];           // fp32 first residual, 134MB
__device__ float g_mean1[NB*CN], g_rstd1[NB*CN], g_pool[NB*CN], g_sum2[NB*CN], g_sumsq2[NB*CN];
__device__ float g_b1e[NB*C2], g_b3e[NB*C2];
__device__ __align__(16) unsigned g_w1p[NB*C2*32];
__device__ __align__(16) unsigned g_w2p[NB*CN*32];
__device__ __align__(16) unsigned g_w3p[NB*C2*32];
__device__ __align__(16) unsigned g_w4p[CN*32];

// res = {lo: a, hi: b}
#define CVT2(res,a,b) asm("cvt.rn.satfinite.bf16x2.f32 %0, %1, %2;" : "=r"(res) : "f"(b), "f"(a))
#define BF2F(u) __bfloat162float(__ushort_as_bfloat16(u))

__device__ __forceinline__ void mma16816(float* d, const unsigned* a, unsigned b0, unsigned b1) {
    asm volatile("mma.sync.aligned.m16n8k16.row.col.f32.bf16.bf16.f32 "
        "{%0,%1,%2,%3}, {%4,%5,%6,%7}, {%8,%9}, {%0,%1,%2,%3};"
        : "+f"(d[0]), "+f"(d[1]), "+f"(d[2]), "+f"(d[3])
        : "r"(a[0]), "r"(a[1]), "r"(a[2]), "r"(a[3]), "r"(b0), "r"(b1));
}

__device__ __forceinline__ void stage_acts_f32(unsigned* sa, const float* src, int n, int p0,
                                               int lane, int wid) {
    const float4* xa = (const float4*)(src + ((size_t)(n * CN + 2 * lane)) * HW) + (p0 >> 2);
    const float4* xb = xa + (HW >> 2);
    #pragma unroll
    for (int j = 0; j < 4; j++) {
        int px4 = wid * 4 + j;
        float4 a = xa[px4], b = xb[px4];
        int p = px4 * 4;
        unsigned v0, v1, v2, v3;
        CVT2(v0, a.x, b.x); CVT2(v1, a.y, b.y); CVT2(v2, a.z, b.z); CVT2(v3, a.w, b.w);
        sa[(p + 0) * 36 + lane] = v0;
        sa[(p + 1) * 36 + lane] = v1;
        sa[(p + 2) * 36 + lane] = v2;
        sa[(p + 3) * 36 + lane] = v3;
    }
}

__device__ __forceinline__ void stage_acts_bf16(unsigned* sa, const unsigned short* src,
                                                int n, int p0, int lane, int wid) {
    const ushort4* ga = (const ushort4*)(src + ((size_t)(n * CN + 2 * lane)) * HW + p0);
    const ushort4* gb = ga + (HW >> 2);
    #pragma unroll
    for (int j = 0; j < 4; j++) {
        int px4 = wid * 4 + j;
        ushort4 a = ga[px4], b = gb[px4];
        int p = px4 * 4;
        sa[(p + 0) * 36 + lane] = (unsigned)a.x | ((unsigned)b.x << 16);
        sa[(p + 1) * 36 + lane] = (unsigned)a.y | ((unsigned)b.y << 16);
        sa[(p + 2) * 36 + lane] = (unsigned)a.z | ((unsigned)b.z << 16);
        sa[(p + 3) * 36 + lane] = (unsigned)a.w | ((unsigned)b.w << 16);
    }
}

__device__ __forceinline__ void copy_w(unsigned* sw, const unsigned* gw, int rows, int t) {
    int r = t >> 5, w = t & 31;
    for (; r < rows; r += 8) sw[r * 36 + w] = gw[r * 32 + w];
}

template<int NT>
__device__ __forceinline__ void gemm_core(const unsigned* sw, const unsigned* sa,
                                          int ms, int ntb, int lane, float* d) {
    int r = ms + (lane >> 2), kp = lane & 3;
    #pragma unroll
    for (int ks = 0; ks < 4; ks++) {
        unsigned a[4];
        a[0] = sw[r * 36 + ks * 8 + kp];
        a[1] = sw[(r + 8) * 36 + ks * 8 + kp];
        a[2] = sw[r * 36 + ks * 8 + kp + 4];
        a[3] = sw[(r + 8) * 36 + ks * 8 + kp + 4];
        #pragma unroll
        for (int nt = 0; nt < NT; nt++) {
            int px = (ntb + nt) * 8 + (lane >> 2);
            unsigned b0 = sa[px * 36 + ks * 8 + kp];
            unsigned b1 = sa[px * 36 + ks * 8 + kp + 4];
            mma16816(d + nt * 4, a, b0, b1);
        }
    }
}

// ---------------- K1: LN1 stats ---------------------------------------------------
__global__ void k_stats1(const float* __restrict__ x) {
    int nc = blockIdx.x;
    const float4* p = (const float4*)(x + (size_t)nc * HW);
    float s = 0.f, q = 0.f;
    for (int j = threadIdx.x; j < HW / 4; j += 256) {
        float4 v = p[j];
        s += v.x + v.y + v.z + v.w;
        q += v.x * v.x + v.y * v.y + v.z * v.z + v.w * v.w;
    }
    __shared__ float rs[8], rq[8];
    for (int o = 16; o; o >>= 1) {
        s += __shfl_down_sync(0xffffffffu, s, o);
        q += __shfl_down_sync(0xffffffffu, q, o);
    }
    if ((threadIdx.x & 31) == 0) { rs[threadIdx.x >> 5] = s; rq[threadIdx.x >> 5] = q; }
    __syncthreads();
    if (threadIdx.x == 0) {
        float S = 0.f, Q = 0.f;
        for (int i = 0; i < 8; i++) { S += rs[i]; Q += rq[i]; }
        float m = S * (1.f / HW);
        g_mean1[nc] = m;
        g_rstd1[nc] = rsqrtf(Q * (1.f / HW) - m * m + EPSV);
    }
}

// ---------------- K2: fold LN1 -> pw1 packed bf16 ---------------------------------
__global__ void k_prep1(const float* __restrict__ ln1w, const float* __restrict__ ln1b,
                        const float* __restrict__ pw1w, const float* __restrict__ pw1b) {
    int n = blockIdx.x, o = threadIdx.x;   // 128
    float bias = pw1b[o], row[CN];
    for (int i = 0; i < CN; i++) {
        float a  = g_rstd1[n * CN + i] * ln1w[i];
        float c0 = ln1b[i] - g_mean1[n * CN + i] * a;
        float w  = pw1w[o * CN + i];
        bias += w * c0;
        row[i] = w * a;
    }
    g_b1e[n * C2 + o] = bias;
    unsigned* dst = g_w1p + (n * C2 + o) * 32;
    for (int j = 0; j < 32; j++) { unsigned pk; CVT2(pk, row[2*j], row[2*j+1]); dst[j] = pk; }
    int idx = n * C2 + o;
    if (idx < NB * CN) { g_pool[idx] = 0.f; g_sum2[idx] = 0.f; g_sumsq2[idx] = 0.f; }
}

// ---------------- K3: pw1 mma.sync GEMM (bf16 out) --------------------------------
__global__ void __launch_bounds__(256) k_pw1(const float* __restrict__ x) {
    __shared__ unsigned sw[C2 * 36];
    __shared__ unsigned sa[128 * 36];
    int t = threadIdx.x, wid = t >> 5, lane = t & 31;
    int n = blockIdx.y, p0 = blockIdx.x * 128;
    copy_w(sw, g_w1p + n * C2 * 32, C2, t);
    stage_acts_f32(sa, x, n, p0, lane, wid);
    __syncthreads();
    float d[64];
    #pragma unroll
    for (int i = 0; i < 64; i++) d[i] = 0.f;
    gemm_core<16>(sw, sa, wid * 16, 0, lane, d);
    int o1 = wid * 16 + (lane >> 2), o2 = o1 + 8;
    float bi1 = g_b1e[n * C2 + o1], bi2 = g_b1e[n * C2 + o2];
    unsigned short* u1 = g_u + (size_t)(n * C2 + o1) * HW + p0;
    unsigned short* u2 = g_u + (size_t)(n * C2 + o2) * HW + p0;
    #pragma unroll
    for (int nt = 0; nt < 16; nt++) {
        int px = nt * 8 + (lane & 3) * 2;
        unsigned pk1, pk2;
        CVT2(pk1, d[nt*4+0] + bi1, d[nt*4+1] + bi1);
        CVT2(pk2, d[nt*4+2] + bi2, d[nt*4+3] + bi2);
        *(unsigned*)(u1 + px) = pk1;
        *(unsigned*)(u2 + px) = pk2;
    }
}

// ---------------- K4: depthwise 3x3 + gate + pool (register-tiled 4x4) ------------
__global__ void __launch_bounds__(256) k_dwgate(const float* __restrict__ dww,
                                                const float* __restrict__ dwb) {
    __shared__ float s[2][18][256];
    __shared__ float red[8];
    int t = threadIdx.x, tx = t & 63, ty = t >> 6;
    int nc = blockIdx.x, n = nc >> 6, c = nc & 63;
    int strip0 = blockIdx.y * 32;
    const unsigned short* u0 = g_u + ((size_t)(n * C2 + c)) * HW;
    const unsigned short* u1 = g_u + ((size_t)(n * C2 + c + 64)) * HW;
    unsigned short* gp = g_g + ((size_t)(n * CN + c)) * HW;
    float w0[9], w1[9];
    #pragma unroll
    for (int k = 0; k < 9; k++) { w0[k] = __ldg(dww + c * 9 + k); w1[k] = __ldg(dww + (c + 64) * 9 + k); }
    float b0 = __ldg(dwb + c), b1 = __ldg(dwb + c + 64);
    float psum = 0.f;
    #pragma unroll 1
    for (int it = 0; it < 2; it++) {
        int base = strip0 + it * 16;
        // load 18 rows x 2ch: 2304 ushort4, 9 per thread
        #pragma unroll
        for (int k = 0; k < 9; k++) {
            int idx = t + k * 256;
            int ch = (idx >= 1152);
            int rem = idx - ch * 1152;
            int lr = rem >> 6, c8 = rem & 63;
            int ar = base - 1 + lr;
            float4 f = make_float4(0.f, 0.f, 0.f, 0.f);
            if ((unsigned)ar < 256u) {
                ushort4 v = *(const ushort4*)((ch ? u1 : u0) + ar * 256 + c8 * 4);
                f = make_float4(BF2F(v.x), BF2F(v.y), BF2F(v.z), BF2F(v.w));
            }
            *(float4*)(&s[ch][lr][c8 * 4]) = f;
        }
        __syncthreads();
        float acc0[16], acc1[16];
        #pragma unroll
        for (int i = 0; i < 16; i++) { acc0[i] = b0; acc1[i] = b1; }
        #pragma unroll
        for (int ch = 0; ch < 2; ch++) {
            float* acc = ch ? acc1 : acc0;
            const float* w = ch ? w1 : w0;
            #pragma unroll
            for (int lr = 0; lr < 6; lr++) {
                const float* row = &s[ch][ty * 4 + lr][0];
                float4 cv = *(const float4*)(row + tx * 4);
                float i0 = tx ? row[tx * 4 - 1] : 0.f;
                float i5 = (tx != 63) ? row[tx * 4 + 4] : 0.f;
                float i1 = cv.x, i2 = cv.y, i3 = cv.z, i4 = cv.w;
                #pragma unroll
                for (int ky = 0; ky < 3; ky++) {
                    int q = lr - ky;
                    if (q >= 0 && q < 4) {
                        acc[q*4+0] += w[ky*3]*i0 + w[ky*3+1]*i1 + w[ky*3+2]*i2;
                        acc[q*4+1] += w[ky*3]*i1 + w[ky*3+1]*i2 + w[ky*3+2]*i3;
                        acc[q*4+2] += w[ky*3]*i2 + w[ky*3+1]*i3 + w[ky*3+2]*i4;
                        acc[q*4+3] += w[ky*3]*i3 + w[ky*3+1]*i4 + w[ky*3+2]*i5;
                    }
                }
            }
        }
        #pragma unroll
        for (int q = 0; q < 4; q++) {
            int r = base + ty * 4 + q;
            float g0 = acc0[q*4+0] * acc1[q*4+0];
            float g1 = acc0[q*4+1] * acc1[q*4+1];
            float g2 = acc0[q*4+2] * acc1[q*4+2];
            float g3 = acc0[q*4+3] * acc1[q*4+3];
            unsigned pk0, pk1;
            CVT2(pk0, g0, g1); CVT2(pk1, g2, g3);
            *(uint2*)(gp + r * 256 + tx * 4) = make_uint2(pk0, pk1);
            psum += (g0 + g1) + (g2 + g3);
        }
        __syncthreads();
    }
    for (int o = 16; o; o >>= 1) psum += __shfl_down_sync(0xffffffffu, psum, o);
    if ((t & 31) == 0) red[t >> 5] = psum;
    __syncthreads();
    if (t < 8) {
        float v = red[t];
        v += __shfl_down_sync(0xffu, v, 4);
        v += __shfl_down_sync(0xffu, v, 2);
        v += __shfl_down_sync(0xffu, v, 1);
        if (t == 0) atomicAdd(&g_pool[nc], v);
    }
}

// ---------------- K5: SCA -> pw2 packed bf16 --------------------------------------
__global__ void k_sca(const float* __restrict__ scaw, const float* __restrict__ scab,
                      const float* __restrict__ pw2w) {
    int n = blockIdx.x, o = threadIdx.x;   // 64
    __shared__ float pm[CN], sc[CN];
    pm[o] = g_pool[n * CN + o] * (1.f / HW);
    __syncthreads();
    float acc = scab[o];
    for (int i = 0; i < CN; i++) acc += scaw[o * CN + i] * pm[i];
    sc[o] = 1.f / (1.f + expf(-acc));
    __syncthreads();
    unsigned* dst = g_w2p + (n * CN + o) * 32;
    for (int j = 0; j < 32; j++) {
        unsigned pk;
        CVT2(pk, pw2w[o * CN + 2*j] * sc[2*j], pw2w[o * CN + 2*j+1] * sc[2*j+1]);
        dst[j] = pk;
    }
}

// ---------------- K6: pw2 mma GEMM + residual + LN2 stats -------------------------
__global__ void __launch_bounds__(256) k_pw2(const float* __restrict__ x,
                                             const float* __restrict__ pw2b,
                                             const float* __restrict__ beta1) {
    __shared__ unsigned sw[CN * 36];
    __shared__ unsigned sa[128 * 36];
    int t = threadIdx.x, wid = t >> 5, lane = t & 31;
    int n = blockIdx.y, p0 = blockIdx.x * 128;
    copy_w(sw, g_w2p + n * CN * 32, CN, t);
    stage_acts_bf16(sa, g_g, n, p0, lane, wid);
    __syncthreads();
    float d[32];
    #pragma unroll
    for (int i = 0; i < 32; i++) d[i] = 0.f;
    gemm_core<8>(sw, sa, (wid & 3) * 16, (wid >> 2) * 8, lane, d);
    int o1 = (wid & 3) * 16 + (lane >> 2), o2 = o1 + 8;
    float b1 = pw2b[o1], b2 = pw2b[o2], t1 = beta1[o1], t2 = beta1[o2];
    size_t off1 = (size_t)(n * CN + o1) * HW + p0;
    size_t off2 = (size_t)(n * CN + o2) * HW + p0;
    float s1 = 0.f, q1 = 0.f, s2 = 0.f, q2 = 0.f;
    #pragma unroll
    for (int nt = 0; nt < 8; nt++) {
        int px = (wid >> 2) * 64 + nt * 8 + (lane & 3) * 2;
        float2 xv1 = *(const float2*)(x + off1 + px);
        float2 xv2 = *(const float2*)(x + off2 + px);
        float2 r1 = make_float2(xv1.x + t1 * (d[nt*4+0] + b1), xv1.y + t1 * (d[nt*4+1] + b1));
        float2 r2 = make_float2(xv2.x + t2 * (d[nt*4+2] + b2), xv2.y + t2 * (d[nt*4+3] + b2));
        *(float2*)(g_x1 + off1 + px) = r1;
        *(float2*)(g_x1 + off2 + px) = r2;
        s1 += r1.x + r1.y; q1 += r1.x * r1.x + r1.y * r1.y;
        s2 += r2.x + r2.y; q2 += r2.x * r2.x + r2.y * r2.y;
    }
    s1 += __shfl_xor_sync(~0u, s1, 1); s1 += __shfl_xor_sync(~0u, s1, 2);
    q1 += __shfl_xor_sync(~0u, q1, 1); q1 += __shfl_xor_sync(~0u, q1, 2);
    s2 += __shfl_xor_sync(~0u, s2, 1); s2 += __shfl_xor_sync(~0u, s2, 2);
    q2 += __shfl_xor_sync(~0u, q2, 1); q2 += __shfl_xor_sync(~0u, q2, 2);
    if ((lane & 3) == 0) {
        atomicAdd(&g_sum2[n * CN + o1], s1);
        atomicAdd(&g_sumsq2[n * CN + o1], q1);
        atomicAdd(&g_sum2[n * CN + o2], s2);
        atomicAdd(&g_sumsq2[n * CN + o2], q2);
    }
}

// ---------------- K7: LN2 -> pw3 packed; pw4 packed -------------------------------
__global__ void k_prep3(const float* __restrict__ ln2w, const float* __restrict__ ln2b,
                        const float* __restrict__ pw3w, const float* __restrict__ pw3b,
                        const float* __restrict__ pw4w) {
    int n = blockIdx.x, o = threadIdx.x;   // 128
    __shared__ float m2[CN], r2[CN];
    if (o < CN) {
        float m = g_sum2[n * CN + o] * (1.f / HW);
        m2[o] = m;
        r2[o] = rsqrtf(g_sumsq2[n * CN + o] * (1.f / HW) - m * m + EPSV);
    }
    __syncthreads();
    float bias = pw3b[o], row[CN];
    for (int i = 0; i < CN; i++) {
        float a  = r2[i] * ln2w[i];
        float c0 = ln2b[i] - m2[i] * a;
        float w  = pw3w[o * CN + i];
        bias += w * c0;
        row[i] = w * a;
    }
    g_b3e[n * C2 + o] = bias;
    unsigned* dst = g_w3p + (n * C2 + o) * 32;
    for (int j = 0; j < 32; j++) { unsigned pk; CVT2(pk, row[2*j], row[2*j+1]); dst[j] = pk; }
    if (n == 0 && o < CN) {
        unsigned* d4 = g_w4p + o * 32;
        for (int j = 0; j < 32; j++) {
            unsigned pk; CVT2(pk, pw4w[o * CN + 2*j], pw4w[o * CN + 2*j+1]);
            d4[j] = pk;
        }
    }
}

// ---------------- K8: pw3 MMA -> gate -> pw4 MMA -> residual -> out ---------------
__global__ void __launch_bounds__(256) k_final(const float* __restrict__ pw4b,
                                               const float* __restrict__ beta2,
                                               float* __restrict__ out) {
    extern __shared__ __align__(16) char smem[];
    float*    x1s  = (float*)smem;                              // [128][66] fp32 = 33792
    unsigned* w3   = (unsigned*)(smem + 33792);                 // 18432
    unsigned* w4   = (unsigned*)(smem + 33792 + 18432);         // 9216
    unsigned* bufB = (unsigned*)(smem + 33792 + 18432 + 9216);  // 18432 (B3 then B4)
    unsigned short* sc2 = (unsigned short*)w3;                  // overlay after pw3
    int t = threadIdx.x, wid = t >> 5, lane = t & 31;
    int n = blockIdx.y, p0 = blockIdx.x * 128;
    copy_w(w3, g_w3p + n * C2 * 32, C2, t);
    copy_w(w4, g_w4p, CN, t);
    {
        const float4* xa = (const float4*)(g_x1 + ((size_t)(n * CN + 2 * lane)) * HW) + (p0 >> 2);
        const float4* xb = xa + (HW >> 2);
        float2* x1s2 = (float2*)x1s;
        #pragma unroll
        for (int j = 0; j < 4; j++) {
            int px4 = wid * 4 + j;
            float4 a = xa[px4], b = xb[px4];
            int p = px4 * 4;
            x1s2[(p + 0) * 33 + lane] = make_float2(a.x, b.x);
            x1s2[(p + 1) * 33 + lane] = make_float2(a.y, b.y);
            x1s2[(p + 2) * 33 + lane] = make_float2(a.z, b.z);
            x1s2[(p + 3) * 33 + lane] = make_float2(a.w, b.w);
            unsigned v0, v1, v2, v3;
            CVT2(v0, a.x, b.x); CVT2(v1, a.y, b.y); CVT2(v2, a.z, b.z); CVT2(v3, a.w, b.w);
            bufB[(p + 0) * 36 + lane] = v0;
            bufB[(p + 1) * 36 + lane] = v1;
            bufB[(p + 2) * 36 + lane] = v2;
            bufB[(p + 3) * 36 + lane] = v3;
        }
    }
    __syncthreads();
    float d[64];
    #pragma unroll
    for (int i = 0; i < 64; i++) d[i] = 0.f;
    gemm_core<16>(w3, bufB, wid * 16, 0, lane, d);
    int r1 = wid * 16 + (lane >> 2), r2 = r1 + 8;
    float b31 = g_b3e[n * C2 + r1], b32 = g_b3e[n * C2 + r2];
    __syncthreads();
    if (wid >= 4) {
        int c1 = r1 - 64, c2 = r2 - 64;
        #pragma unroll
        for (int nt = 0; nt < 16; nt++) {
            int px = nt * 8 + (lane & 3) * 2;
            sc2[px * 72 + c1]       = __bfloat16_as_ushort(__float2bfloat16_rn(d[nt*4+0] + b31));
            sc2[(px + 1) * 72 + c1] = __bfloat16_as_ushort(__float2bfloat16_rn(d[nt*4+1] + b31));
            sc2[px * 72 + c2]       = __bfloat16_as_ushort(__float2bfloat16_rn(d[nt*4+2] + b32));
            sc2[(px + 1) * 72 + c2] = __bfloat16_as_ushort(__float2bfloat16_rn(d[nt*4+3] + b32));
        }
    }
    __syncthreads();
    if (wid < 4) {
        unsigned short* b4s = (unsigned short*)bufB;
        #pragma unroll
        for (int nt = 0; nt < 16; nt++) {
            int px = nt * 8 + (lane & 3) * 2;
            float h0 = BF2F(sc2[px * 72 + r1]);
            float h1 = BF2F(sc2[(px + 1) * 72 + r1]);
            float h2 = BF2F(sc2[px * 72 + r2]);
            float h3 = BF2F(sc2[(px + 1) * 72 + r2]);
            b4s[px * 72 + r1]       = __bfloat16_as_ushort(__float2bfloat16_rn((d[nt*4+0] + b31) * h0));
            b4s[(px + 1) * 72 + r1] = __bfloat16_as_ushort(__float2bfloat16_rn((d[nt*4+1] + b31) * h1));
            b4s[px * 72 + r2]       = __bfloat16_as_ushort(__float2bfloat16_rn((d[nt*4+2] + b32) * h2));
            b4s[(px + 1) * 72 + r2] = __bfloat16_as_ushort(__float2bfloat16_rn((d[nt*4+3] + b32) * h3));
        }
    }
    __syncthreads();
    float e[32];
    #pragma unroll
    for (int i = 0; i < 32; i++) e[i] = 0.f;
    gemm_core<8>(w4, bufB, (wid & 3) * 16, (wid >> 2) * 8, lane, e);
    int o1 = (wid & 3) * 16 + (lane >> 2), o2 = o1 + 8;
    float b41 = pw4b[o1], b42 = pw4b[o2], t41 = beta2[o1], t42 = beta2[o2];
    float* op1 = out + (size_t)(n * CN + o1) * HW + p0;
    float* op2 = out + (size_t)(n * CN + o2) * HW + p0;
    #pragma unroll
    for (int nt = 0; nt < 8; nt++) {
        int px = (wid >> 2) * 64 + nt * 8 + (lane & 3) * 2;
        float2 r1v, r2v;
        r1v.x = x1s[px * 66 + o1]       + t41 * (e[nt*4+0] + b41);
        r1v.y = x1s[(px + 1) * 66 + o1] + t41 * (e[nt*4+1] + b41);
        r2v.x = x1s[px * 66 + o2]       + t42 * (e[nt*4+2] + b42);
        r2v.y = x1s[(px + 1) * 66 + o2] + t42 * (e[nt*4+3] + b42);
        *(float2*)(op1 + px) = r1v;
        *(float2*)(op2 + px) = r2v;
    }
}

// ---------------- host ------------------------------------------------------------
extern "C" void kernel_launch(void* const* d_in, const int* in_sizes, int n_in,
                              void* d_out, int out_size) {
    const float* x     = (const float*)d_in[0];
    const float* ln1w  = (const float*)d_in[1];
    const float* ln1b  = (const float*)d_in[2];
    const float* pw1w  = (const float*)d_in[3];
    const float* pw1b  = (const float*)d_in[4];
    const float* dww   = (const float*)d_in[5];
    const float* dwb   = (const float*)d_in[6];
    const float* scaw  = (const float*)d_in[7];
    const float* scab  = (const float*)d_in[8];
    const float* pw2w  = (const float*)d_in[9];
    const float* pw2b  = (const float*)d_in[10];
    const float* ln2w  = (const float*)d_in[11];
    const float* ln2b  = (const float*)d_in[12];
    const float* pw3w  = (const float*)d_in[13];
    const float* pw3b  = (const float*)d_in[14];
    const float* pw4w  = (const float*)d_in[15];
    const float* pw4b  = (const float*)d_in[16];
    const float* beta1 = (const float*)d_in[17];
    const float* beta2 = (const float*)d_in[18];

    cudaFuncSetAttribute(k_final, cudaFuncAttributeMaxDynamicSharedMemorySize, 80 * 1024);

    k_stats1<<<NB * CN, 256>>>(x);
    k_prep1<<<NB, C2>>>(ln1w, ln1b, pw1w, pw1b);
    k_pw1<<<dim3(512, NB), 256>>>(x);
    k_dwgate<<<dim3(NB * CN, 8), 256>>>(dww, dwb);
    k_sca<<<NB, CN>>>(scaw, scab, pw2w);
    k_pw2<<<dim3(512, NB), 256>>>(x, pw2b, beta1);
    k_prep3<<<NB, C2>>>(ln2w, ln2b, pw3w, pw3b, pw4w);
    k_final<<<dim3(512, NB), 256, 80 * 1024>>>(pw4b, beta2, (float*)d_out);
}

// round 13
// speedup vs baseline: 2.3982x; 1.0717x over previous
#include <cuda_runtime.h>
#include <cuda_bf16.h>
#include <cstdint>

#define HW 65536
#define CN 64
#define C2 128
#define NB 8
#define EPSV 1e-6f

__device__ unsigned short g_u[(size_t)NB*C2*HW];   // bf16 pw1 output, 134MB
__device__ unsigned short g_g[(size_t)NB*CN*HW];   // bf16 gated, 67MB
__device__ float g_x1[(size_t)NB*CN*HW];           // fp32 first residual, 134MB
__device__ float g_mean1[NB*CN], g_rstd1[NB*CN], g_pool[NB*CN], g_sum2[NB*CN], g_sumsq2[NB*CN];
__device__ float g_b1e[NB*C2], g_b3e[NB*C2];
__device__ __align__(16) unsigned g_w1p[NB*C2*32];
__device__ __align__(16) unsigned g_w2p[NB*CN*32];
__device__ __align__(16) unsigned g_w3p[NB*C2*32];
__device__ __align__(16) unsigned g_w4p[CN*32];

// res = {lo: a, hi: b}
#define CVT2(res,a,b) asm("cvt.rn.satfinite.bf16x2.f32 %0, %1, %2;" : "=r"(res) : "f"(b), "f"(a))
#define BF2F(u) __bfloat162float(__ushort_as_bfloat16(u))

__device__ __forceinline__ void mma16816(float* d, const unsigned* a, unsigned b0, unsigned b1) {
    asm volatile("mma.sync.aligned.m16n8k16.row.col.f32.bf16.bf16.f32 "
        "{%0,%1,%2,%3}, {%4,%5,%6,%7}, {%8,%9}, {%0,%1,%2,%3};"
        : "+f"(d[0]), "+f"(d[1]), "+f"(d[2]), "+f"(d[3])
        : "r"(a[0]), "r"(a[1]), "r"(a[2]), "r"(a[3]), "r"(b0), "r"(b1));
}

// 512-thread staging: fp32 ch-major -> bf16 [128px][36 words]
__device__ __forceinline__ void stage_acts_f32(unsigned* sa, const float* src, int n, int p0,
                                               int lane, int wid) {
    const float4* xa = (const float4*)(src + ((size_t)(n * CN + 2 * lane)) * HW) + (p0 >> 2);
    const float4* xb = xa + (HW >> 2);
    #pragma unroll
    for (int j = 0; j < 2; j++) {
        int px4 = wid * 2 + j;
        float4 a = xa[px4], b = xb[px4];
        int p = px4 * 4;
        unsigned v0, v1, v2, v3;
        CVT2(v0, a.x, b.x); CVT2(v1, a.y, b.y); CVT2(v2, a.z, b.z); CVT2(v3, a.w, b.w);
        sa[(p + 0) * 36 + lane] = v0;
        sa[(p + 1) * 36 + lane] = v1;
        sa[(p + 2) * 36 + lane] = v2;
        sa[(p + 3) * 36 + lane] = v3;
    }
}

__device__ __forceinline__ void stage_acts_bf16(unsigned* sa, const unsigned short* src,
                                                int n, int p0, int lane, int wid) {
    const ushort4* ga = (const ushort4*)(src + ((size_t)(n * CN + 2 * lane)) * HW + p0);
    const ushort4* gb = ga + (HW >> 2);
    #pragma unroll
    for (int j = 0; j < 2; j++) {
        int px4 = wid * 2 + j;
        ushort4 a = ga[px4], b = gb[px4];
        int p = px4 * 4;
        sa[(p + 0) * 36 + lane] = (unsigned)a.x | ((unsigned)b.x << 16);
        sa[(p + 1) * 36 + lane] = (unsigned)a.y | ((unsigned)b.y << 16);
        sa[(p + 2) * 36 + lane] = (unsigned)a.z | ((unsigned)b.z << 16);
        sa[(p + 3) * 36 + lane] = (unsigned)a.w | ((unsigned)b.w << 16);
    }
}

// 512-thread weight copy
__device__ __forceinline__ void copy_w(unsigned* sw, const unsigned* gw, int rows, int t) {
    int r = t >> 5, w = t & 31;
    for (; r < rows; r += 16) sw[r * 36 + w] = gw[r * 32 + w];
}

template<int NT>
__device__ __forceinline__ void gemm_core(const unsigned* sw, const unsigned* sa,
                                          int ms, int ntb, int lane, float* d) {
    int r = ms + (lane >> 2), kp = lane & 3;
    #pragma unroll
    for (int ks = 0; ks < 4; ks++) {
        unsigned a[4];
        a[0] = sw[r * 36 + ks * 8 + kp];
        a[1] = sw[(r + 8) * 36 + ks * 8 + kp];
        a[2] = sw[r * 36 + ks * 8 + kp + 4];
        a[3] = sw[(r + 8) * 36 + ks * 8 + kp + 4];
        #pragma unroll
        for (int nt = 0; nt < NT; nt++) {
            int px = (ntb + nt) * 8 + (lane >> 2);
            unsigned b0 = sa[px * 36 + ks * 8 + kp];
            unsigned b1 = sa[px * 36 + ks * 8 + kp + 4];
            mma16816(d + nt * 4, a, b0, b1);
        }
    }
}

// ---------------- K1: LN1 stats ---------------------------------------------------
__global__ void __launch_bounds__(512) k_stats1(const float* __restrict__ x) {
    int nc = blockIdx.x;
    const float4* p = (const float4*)(x + (size_t)nc * HW);
    float s = 0.f, q = 0.f;
    for (int j = threadIdx.x; j < HW / 4; j += 512) {
        float4 v = p[j];
        s += v.x + v.y + v.z + v.w;
        q += v.x * v.x + v.y * v.y + v.z * v.z + v.w * v.w;
    }
    __shared__ float rs[16], rq[16];
    for (int o = 16; o; o >>= 1) {
        s += __shfl_down_sync(0xffffffffu, s, o);
        q += __shfl_down_sync(0xffffffffu, q, o);
    }
    if ((threadIdx.x & 31) == 0) { rs[threadIdx.x >> 5] = s; rq[threadIdx.x >> 5] = q; }
    __syncthreads();
    if (threadIdx.x == 0) {
        float S = 0.f, Q = 0.f;
        for (int i = 0; i < 16; i++) { S += rs[i]; Q += rq[i]; }
        float m = S * (1.f / HW);
        g_mean1[nc] = m;
        g_rstd1[nc] = rsqrtf(Q * (1.f / HW) - m * m + EPSV);
    }
}

// ---------------- K2: fold LN1 -> pw1 packed bf16 ---------------------------------
__global__ void k_prep1(const float* __restrict__ ln1w, const float* __restrict__ ln1b,
                        const float* __restrict__ pw1w, const float* __restrict__ pw1b) {
    int n = blockIdx.x, o = threadIdx.x;   // 128
    float bias = pw1b[o], row[CN];
    for (int i = 0; i < CN; i++) {
        float a  = g_rstd1[n * CN + i] * ln1w[i];
        float c0 = ln1b[i] - g_mean1[n * CN + i] * a;
        float w  = pw1w[o * CN + i];
        bias += w * c0;
        row[i] = w * a;
    }
    g_b1e[n * C2 + o] = bias;
    unsigned* dst = g_w1p + (n * C2 + o) * 32;
    for (int j = 0; j < 32; j++) { unsigned pk; CVT2(pk, row[2*j], row[2*j+1]); dst[j] = pk; }
    int idx = n * C2 + o;
    if (idx < NB * CN) { g_pool[idx] = 0.f; g_sum2[idx] = 0.f; g_sumsq2[idx] = 0.f; }
}

// ---------------- K3: pw1 mma.sync GEMM (512 thr, bf16 out) -----------------------
__global__ void __launch_bounds__(512) k_pw1(const float* __restrict__ x) {
    __shared__ unsigned sw[C2 * 36];
    __shared__ unsigned sa[128 * 36];
    int t = threadIdx.x, wid = t >> 5, lane = t & 31;
    int n = blockIdx.y, p0 = blockIdx.x * 128;
    copy_w(sw, g_w1p + n * C2 * 32, C2, t);
    stage_acts_f32(sa, x, n, p0, lane, wid);
    __syncthreads();
    float d[32];
    #pragma unroll
    for (int i = 0; i < 32; i++) d[i] = 0.f;
    gemm_core<8>(sw, sa, (wid & 7) * 16, (wid >> 3) * 8, lane, d);
    int o1 = (wid & 7) * 16 + (lane >> 2), o2 = o1 + 8;
    float bi1 = g_b1e[n * C2 + o1], bi2 = g_b1e[n * C2 + o2];
    unsigned short* u1 = g_u + (size_t)(n * C2 + o1) * HW + p0;
    unsigned short* u2 = g_u + (size_t)(n * C2 + o2) * HW + p0;
    #pragma unroll
    for (int nt = 0; nt < 8; nt++) {
        int px = (wid >> 3) * 64 + nt * 8 + (lane & 3) * 2;
        unsigned pk1, pk2;
        CVT2(pk1, d[nt*4+0] + bi1, d[nt*4+1] + bi1);
        CVT2(pk2, d[nt*4+2] + bi2, d[nt*4+3] + bi2);
        *(unsigned*)(u1 + px) = pk1;
        *(unsigned*)(u2 + px) = pk2;
    }
}

// ---------------- K4: depthwise 3x3 + gate + pool (register-tiled 4x4) ------------
__global__ void __launch_bounds__(256) k_dwgate(const float* __restrict__ dww,
                                                const float* __restrict__ dwb) {
    __shared__ float s[2][18][256];
    __shared__ float red[8];
    int t = threadIdx.x, tx = t & 63, ty = t >> 6;
    int nc = blockIdx.x, n = nc >> 6, c = nc & 63;
    int strip0 = blockIdx.y * 32;
    const unsigned short* u0 = g_u + ((size_t)(n * C2 + c)) * HW;
    const unsigned short* u1 = g_u + ((size_t)(n * C2 + c + 64)) * HW;
    unsigned short* gp = g_g + ((size_t)(n * CN + c)) * HW;
    float w0[9], w1[9];
    #pragma unroll
    for (int k = 0; k < 9; k++) { w0[k] = __ldg(dww + c * 9 + k); w1[k] = __ldg(dww + (c + 64) * 9 + k); }
    float b0 = __ldg(dwb + c), b1 = __ldg(dwb + c + 64);
    float psum = 0.f;
    #pragma unroll 1
    for (int it = 0; it < 2; it++) {
        int base = strip0 + it * 16;
        #pragma unroll
        for (int k = 0; k < 9; k++) {
            int idx = t + k * 256;
            int ch = (idx >= 1152);
            int rem = idx - ch * 1152;
            int lr = rem >> 6, c8 = rem & 63;
            int ar = base - 1 + lr;
            float4 f = make_float4(0.f, 0.f, 0.f, 0.f);
            if ((unsigned)ar < 256u) {
                ushort4 v = *(const ushort4*)((ch ? u1 : u0) + ar * 256 + c8 * 4);
                f = make_float4(BF2F(v.x), BF2F(v.y), BF2F(v.z), BF2F(v.w));
            }
            *(float4*)(&s[ch][lr][c8 * 4]) = f;
        }
        __syncthreads();
        float acc0[16], acc1[16];
        #pragma unroll
        for (int i = 0; i < 16; i++) { acc0[i] = b0; acc1[i] = b1; }
        #pragma unroll
        for (int ch = 0; ch < 2; ch++) {
            float* acc = ch ? acc1 : acc0;
            const float* w = ch ? w1 : w0;
            #pragma unroll
            for (int lr = 0; lr < 6; lr++) {
                const float* row = &s[ch][ty * 4 + lr][0];
                float4 cv = *(const float4*)(row + tx * 4);
                float i0 = tx ? row[tx * 4 - 1] : 0.f;
                float i5 = (tx != 63) ? row[tx * 4 + 4] : 0.f;
                float i1 = cv.x, i2 = cv.y, i3 = cv.z, i4 = cv.w;
                #pragma unroll
                for (int ky = 0; ky < 3; ky++) {
                    int q = lr - ky;
                    if (q >= 0 && q < 4) {
                        acc[q*4+0] += w[ky*3]*i0 + w[ky*3+1]*i1 + w[ky*3+2]*i2;
                        acc[q*4+1] += w[ky*3]*i1 + w[ky*3+1]*i2 + w[ky*3+2]*i3;
                        acc[q*4+2] += w[ky*3]*i2 + w[ky*3+1]*i3 + w[ky*3+2]*i4;
                        acc[q*4+3] += w[ky*3]*i3 + w[ky*3+1]*i4 + w[ky*3+2]*i5;
                    }
                }
            }
        }
        #pragma unroll
        for (int q = 0; q < 4; q++) {
            int r = base + ty * 4 + q;
            float g0 = acc0[q*4+0] * acc1[q*4+0];
            float g1 = acc0[q*4+1] * acc1[q*4+1];
            float g2 = acc0[q*4+2] * acc1[q*4+2];
            float g3 = acc0[q*4+3] * acc1[q*4+3];
            unsigned pk0, pk1;
            CVT2(pk0, g0, g1); CVT2(pk1, g2, g3);
            *(uint2*)(gp + r * 256 + tx * 4) = make_uint2(pk0, pk1);
            psum += (g0 + g1) + (g2 + g3);
        }
        __syncthreads();
    }
    for (int o = 16; o; o >>= 1) psum += __shfl_down_sync(0xffffffffu, psum, o);
    if ((t & 31) == 0) red[t >> 5] = psum;
    __syncthreads();
    if (t < 8) {
        float v = red[t];
        v += __shfl_down_sync(0xffu, v, 4);
        v += __shfl_down_sync(0xffu, v, 2);
        v += __shfl_down_sync(0xffu, v, 1);
        if (t == 0) atomicAdd(&g_pool[nc], v);
    }
}

// ---------------- K5: SCA -> pw2 packed bf16 --------------------------------------
__global__ void k_sca(const float* __restrict__ scaw, const float* __restrict__ scab,
                      const float* __restrict__ pw2w) {
    int n = blockIdx.x, o = threadIdx.x;   // 64
    __shared__ float pm[CN], sc[CN];
    pm[o] = g_pool[n * CN + o] * (1.f / HW);
    __syncthreads();
    float acc = scab[o];
    for (int i = 0; i < CN; i++) acc += scaw[o * CN + i] * pm[i];
    sc[o] = 1.f / (1.f + expf(-acc));
    __syncthreads();
    unsigned* dst = g_w2p + (n * CN + o) * 32;
    for (int j = 0; j < 32; j++) {
        unsigned pk;
        CVT2(pk, pw2w[o * CN + 2*j] * sc[2*j], pw2w[o * CN + 2*j+1] * sc[2*j+1]);
        dst[j] = pk;
    }
}

// ---------------- K6: pw2 mma GEMM + residual + LN2 stats (512 thr) ---------------
__global__ void __launch_bounds__(512) k_pw2(const float* __restrict__ x,
                                             const float* __restrict__ pw2b,
                                             const float* __restrict__ beta1) {
    __shared__ unsigned sw[CN * 36];
    __shared__ unsigned sa[128 * 36];
    int t = threadIdx.x, wid = t >> 5, lane = t & 31;
    int n = blockIdx.y, p0 = blockIdx.x * 128;
    copy_w(sw, g_w2p + n * CN * 32, CN, t);
    stage_acts_bf16(sa, g_g, n, p0, lane, wid);
    __syncthreads();
    float d[16];
    #pragma unroll
    for (int i = 0; i < 16; i++) d[i] = 0.f;
    gemm_core<4>(sw, sa, (wid & 3) * 16, (wid >> 2) * 4, lane, d);
    int o1 = (wid & 3) * 16 + (lane >> 2), o2 = o1 + 8;
    float b1 = pw2b[o1], b2 = pw2b[o2], t1 = beta1[o1], t2 = beta1[o2];
    size_t off1 = (size_t)(n * CN + o1) * HW + p0;
    size_t off2 = (size_t)(n * CN + o2) * HW + p0;
    float s1 = 0.f, q1 = 0.f, s2 = 0.f, q2 = 0.f;
    #pragma unroll
    for (int nt = 0; nt < 4; nt++) {
        int px = (wid >> 2) * 32 + nt * 8 + (lane & 3) * 2;
        float2 xv1 = *(const float2*)(x + off1 + px);
        float2 xv2 = *(const float2*)(x + off2 + px);
        float2 r1 = make_float2(xv1.x + t1 * (d[nt*4+0] + b1), xv1.y + t1 * (d[nt*4+1] + b1));
        float2 r2 = make_float2(xv2.x + t2 * (d[nt*4+2] + b2), xv2.y + t2 * (d[nt*4+3] + b2));
        *(float2*)(g_x1 + off1 + px) = r1;
        *(float2*)(g_x1 + off2 + px) = r2;
        s1 += r1.x + r1.y; q1 += r1.x * r1.x + r1.y * r1.y;
        s2 += r2.x + r2.y; q2 += r2.x * r2.x + r2.y * r2.y;
    }
    s1 += __shfl_xor_sync(~0u, s1, 1); s1 += __shfl_xor_sync(~0u, s1, 2);
    q1 += __shfl_xor_sync(~0u, q1, 1); q1 += __shfl_xor_sync(~0u, q1, 2);
    s2 += __shfl_xor_sync(~0u, s2, 1); s2 += __shfl_xor_sync(~0u, s2, 2);
    q2 += __shfl_xor_sync(~0u, q2, 1); q2 += __shfl_xor_sync(~0u, q2, 2);
    if ((lane & 3) == 0) {
        atomicAdd(&g_sum2[n * CN + o1], s1);
        atomicAdd(&g_sumsq2[n * CN + o1], q1);
        atomicAdd(&g_sum2[n * CN + o2], s2);
        atomicAdd(&g_sumsq2[n * CN + o2], q2);
    }
}

// ---------------- K7: LN2 -> pw3 packed; pw4 packed -------------------------------
__global__ void k_prep3(const float* __restrict__ ln2w, const float* __restrict__ ln2b,
                        const float* __restrict__ pw3w, const float* __restrict__ pw3b,
                        const float* __restrict__ pw4w) {
    int n = blockIdx.x, o = threadIdx.x;   // 128
    __shared__ float m2[CN], r2[CN];
    if (o < CN) {
        float m = g_sum2[n * CN + o] * (1.f / HW);
        m2[o] = m;
        r2[o] = rsqrtf(g_sumsq2[n * CN + o] * (1.f / HW) - m * m + EPSV);
    }
    __syncthreads();
    float bias = pw3b[o], row[CN];
    for (int i = 0; i < CN; i++) {
        float a  = r2[i] * ln2w[i];
        float c0 = ln2b[i] - m2[i] * a;
        float w  = pw3w[o * CN + i];
        bias += w * c0;
        row[i] = w * a;
    }
    g_b3e[n * C2 + o] = bias;
    unsigned* dst = g_w3p + (n * C2 + o) * 32;
    for (int j = 0; j < 32; j++) { unsigned pk; CVT2(pk, row[2*j], row[2*j+1]); dst[j] = pk; }
    if (n == 0 && o < CN) {
        unsigned* d4 = g_w4p + o * 32;
        for (int j = 0; j < 32; j++) {
            unsigned pk; CVT2(pk, pw4w[o * CN + 2*j], pw4w[o * CN + 2*j+1]);
            d4[j] = pk;
        }
    }
}

// ---------------- K8: pw3 MMA -> gate -> pw4 MMA -> residual -> out (512 thr) -----
__global__ void __launch_bounds__(512) k_final(const float* __restrict__ pw4b,
                                               const float* __restrict__ beta2,
                                               float* __restrict__ out) {
    extern __shared__ __align__(16) char smem[];
    float*    x1s  = (float*)smem;                              // [128][66] fp32 = 33792
    unsigned* w3   = (unsigned*)(smem + 33792);                 // 18432
    unsigned* w4   = (unsigned*)(smem + 33792 + 18432);         // 9216
    unsigned* bufB = (unsigned*)(smem + 33792 + 18432 + 9216);  // 18432 (B3 then B4)
    unsigned short* sc2 = (unsigned short*)w3;                  // overlay after pw3
    int t = threadIdx.x, wid = t >> 5, lane = t & 31;
    int n = blockIdx.y, p0 = blockIdx.x * 128;
    copy_w(w3, g_w3p + n * C2 * 32, C2, t);
    copy_w(w4, g_w4p, CN, t);
    {
        const float4* xa = (const float4*)(g_x1 + ((size_t)(n * CN + 2 * lane)) * HW) + (p0 >> 2);
        const float4* xb = xa + (HW >> 2);
        float2* x1s2 = (float2*)x1s;
        #pragma unroll
        for (int j = 0; j < 2; j++) {
            int px4 = wid * 2 + j;
            float4 a = xa[px4], b = xb[px4];
            int p = px4 * 4;
            x1s2[(p + 0) * 33 + lane] = make_float2(a.x, b.x);
            x1s2[(p + 1) * 33 + lane] = make_float2(a.y, b.y);
            x1s2[(p + 2) * 33 + lane] = make_float2(a.z, b.z);
            x1s2[(p + 3) * 33 + lane] = make_float2(a.w, b.w);
            unsigned v0, v1, v2, v3;
            CVT2(v0, a.x, b.x); CVT2(v1, a.y, b.y); CVT2(v2, a.z, b.z); CVT2(v3, a.w, b.w);
            bufB[(p + 0) * 36 + lane] = v0;
            bufB[(p + 1) * 36 + lane] = v1;
            bufB[(p + 2) * 36 + lane] = v2;
            bufB[(p + 3) * 36 + lane] = v3;
        }
    }
    __syncthreads();
    float d[32];
    #pragma unroll
    for (int i = 0; i < 32; i++) d[i] = 0.f;
    gemm_core<8>(w3, bufB, (wid & 7) * 16, (wid >> 3) * 8, lane, d);
    int r1 = (wid & 7) * 16 + (lane >> 2), r2 = r1 + 8;
    int pgrp = (wid >> 3) * 64;
    float b31 = g_b3e[n * C2 + r1], b32 = g_b3e[n * C2 + r2];
    __syncthreads();   // all warps done reading w3/bufB
    if ((wid & 7) >= 4) {   // hi strips: write y_hi bf16 into sc2 [px][72]
        int c1 = r1 - 64, c2 = r2 - 64;
        #pragma unroll
        for (int nt = 0; nt < 8; nt++) {
            int px = pgrp + nt * 8 + (lane & 3) * 2;
            sc2[px * 72 + c1]       = __bfloat16_as_ushort(__float2bfloat16_rn(d[nt*4+0] + b31));
            sc2[(px + 1) * 72 + c1] = __bfloat16_as_ushort(__float2bfloat16_rn(d[nt*4+1] + b31));
            sc2[px * 72 + c2]       = __bfloat16_as_ushort(__float2bfloat16_rn(d[nt*4+2] + b32));
            sc2[(px + 1) * 72 + c2] = __bfloat16_as_ushort(__float2bfloat16_rn(d[nt*4+3] + b32));
        }
    }
    __syncthreads();
    if ((wid & 7) < 4) {    // lo strips: gate, write B4 bf16 into bufB [px][72]
        unsigned short* b4s = (unsigned short*)bufB;
        #pragma unroll
        for (int nt = 0; nt < 8; nt++) {
            int px = pgrp + nt * 8 + (lane & 3) * 2;
            float h0 = BF2F(sc2[px * 72 + r1]);
            float h1 = BF2F(sc2[(px + 1) * 72 + r1]);
            float h2 = BF2F(sc2[px * 72 + r2]);
            float h3 = BF2F(sc2[(px + 1) * 72 + r2]);
            b4s[px * 72 + r1]       = __bfloat16_as_ushort(__float2bfloat16_rn((d[nt*4+0] + b31) * h0));
            b4s[(px + 1) * 72 + r1] = __bfloat16_as_ushort(__float2bfloat16_rn((d[nt*4+1] + b31) * h1));
            b4s[px * 72 + r2]       = __bfloat16_as_ushort(__float2bfloat16_rn((d[nt*4+2] + b32) * h2));
            b4s[(px + 1) * 72 + r2] = __bfloat16_as_ushort(__float2bfloat16_rn((d[nt*4+3] + b32) * h3));
        }
    }
    __syncthreads();
    float e[16];
    #pragma unroll
    for (int i = 0; i < 16; i++) e[i] = 0.f;
    gemm_core<4>(w4, bufB, (wid & 3) * 16, (wid >> 2) * 4, lane, e);
    int o1 = (wid & 3) * 16 + (lane >> 2), o2 = o1 + 8;
    float b41 = pw4b[o1], b42 = pw4b[o2], t41 = beta2[o1], t42 = beta2[o2];
    float* op1 = out + (size_t)(n * CN + o1) * HW + p0;
    float* op2 = out + (size_t)(n * CN + o2) * HW + p0;
    #pragma unroll
    for (int nt = 0; nt < 4; nt++) {
        int px = (wid >> 2) * 32 + nt * 8 + (lane & 3) * 2;
        float2 r1v, r2v;
        r1v.x = x1s[px * 66 + o1]       + t41 * (e[nt*4+0] + b41);
        r1v.y = x1s[(px + 1) * 66 + o1] + t41 * (e[nt*4+1] + b41);
        r2v.x = x1s[px * 66 + o2]       + t42 * (e[nt*4+2] + b42);
        r2v.y = x1s[(px + 1) * 66 + o2] + t42 * (e[nt*4+3] + b42);
        *(float2*)(op1 + px) = r1v;
        *(float2*)(op2 + px) = r2v;
    }
}

// ---------------- host ------------------------------------------------------------
extern "C" void kernel_launch(void* const* d_in, const int* in_sizes, int n_in,
                              void* d_out, int out_size) {
    const float* x     = (const float*)d_in[0];
    const float* ln1w  = (const float*)d_in[1];
    const float* ln1b  = (const float*)d_in[2];
    const float* pw1w  = (const float*)d_in[3];
    const float* pw1b  = (const float*)d_in[4];
    const float* dww   = (const float*)d_in[5];
    const float* dwb   = (const float*)d_in[6];
    const float* scaw  = (const float*)d_in[7];
    const float* scab  = (const float*)d_in[8];
    const float* pw2w  = (const float*)d_in[9];
    const float* pw2b  = (const float*)d_in[10];
    const float* ln2w  = (const float*)d_in[11];
    const float* ln2b  = (const float*)d_in[12];
    const float* pw3w  = (const float*)d_in[13];
    const float* pw3b  = (const float*)d_in[14];
    const float* pw4w  = (const float*)d_in[15];
    const float* pw4b  = (const float*)d_in[16];
    const float* beta1 = (const float*)d_in[17];
    const float* beta2 = (const float*)d_in[18];

    cudaFuncSetAttribute(k_final, cudaFuncAttributeMaxDynamicSharedMemorySize, 80 * 1024);

    k_stats1<<<NB * CN, 512>>>(x);
    k_prep1<<<NB, C2>>>(ln1w, ln1b, pw1w, pw1b);
    k_pw1<<<dim3(512, NB), 512>>>(x);
    k_dwgate<<<dim3(NB * CN, 8), 256>>>(dww, dwb);
    k_sca<<<NB, CN>>>(scaw, scab, pw2w);
    k_pw2<<<dim3(512, NB), 512>>>(x, pw2b, beta1);
    k_prep3<<<NB, C2>>>(ln2w, ln2b, pw3w, pw3b, pw4w);
    k_final<<<dim3(512, NB), 512, 80 * 1024>>>(pw4b, beta2, (float*)d_out);
}